// round 2
// baseline (speedup 1.0000x reference)
#include <cuda_runtime.h>
#include <math.h>

#define BATCH 2
#define SEQ   4096
#define DMODEL 768
#define NHEAD 12
#define HDIM  64
#define NTOK  (BATCH*SEQ)   // 8192

// ---------------- scratch (no allocations allowed) ----------------
__device__ float g_q[(size_t)BATCH*NHEAD*SEQ*HDIM];    // [B,H,S,64]
__device__ float g_k[(size_t)BATCH*NHEAD*SEQ*HDIM];
__device__ float g_v[(size_t)BATCH*NHEAD*SEQ*HDIM];
__device__ float g_pre[(size_t)NTOK*DMODEL];           // [B,S,768]

// =================================================================
// GEMM: out = X @ W^T + bias
//   X: [NTOK, 768]  (token-major, contiguous in k)
//   W: [768, 768]   (row-major, W[o][k])  -> both operands k-contiguous
// qkv_mode=1: write to [B,H,S,64] layout (blockIdx.y == head)
// qkv_mode=0: write to [NTOK, 768]
// Tile: 64x64, BK=16, 256 threads, 4x4 microtile, 2-deep LDG pipeline.
// =================================================================
__global__ __launch_bounds__(256) void gemm64_kernel(
    const float* __restrict__ X, const float* __restrict__ W,
    const float* __restrict__ bias, float* __restrict__ out, int qkv_mode)
{
    __shared__ float As[16][68];   // [k][m], pad 68 keeps float4 alignment
    __shared__ float Bs[16][68];   // [k][n]

    const int tid = threadIdx.x;
    const int ty  = tid >> 4;      // 0..15 -> m group
    const int tx  = tid & 15;      // 0..15 -> n group
    const int row0 = blockIdx.x * 64;
    const int col0 = blockIdx.y * 64;

    const int lm = tid >> 2;         // 0..63 row within tile
    const int lc = (tid & 3) << 2;   // 0,4,8,12 k-offset

    const float* xg = X + (size_t)(row0 + lm) * DMODEL + lc;
    const float* wg = W + (size_t)(col0 + lm) * DMODEL + lc;

    float acc[4][4] = {};

    // prologue load
    float4 xa = *(const float4*)(xg);
    float4 wa = *(const float4*)(wg);

    for (int k0 = 0; k0 < DMODEL; k0 += 16) {
        __syncthreads();   // previous iter's reads done before overwrite
        As[lc+0][lm] = xa.x; As[lc+1][lm] = xa.y; As[lc+2][lm] = xa.z; As[lc+3][lm] = xa.w;
        Bs[lc+0][lm] = wa.x; Bs[lc+1][lm] = wa.y; Bs[lc+2][lm] = wa.z; Bs[lc+3][lm] = wa.w;
        __syncthreads();
        // prefetch next k-tile while the FFMA block below runs
        if (k0 + 16 < DMODEL) {
            xa = *(const float4*)(xg + k0 + 16);
            wa = *(const float4*)(wg + k0 + 16);
        }
#pragma unroll
        for (int kk = 0; kk < 16; kk++) {
            float4 a = *(const float4*)&As[kk][ty << 2];   // broadcast across tx
            float4 b = *(const float4*)&Bs[kk][tx << 2];   // consecutive across tx
            float ar[4] = {a.x, a.y, a.z, a.w};
            float br[4] = {b.x, b.y, b.z, b.w};
#pragma unroll
            for (int i = 0; i < 4; i++)
#pragma unroll
                for (int j = 0; j < 4; j++)
                    acc[i][j] += ar[i] * br[j];
        }
    }

    float4 bb = *(const float4*)&bias[col0 + (tx << 2)];
    float br4[4] = {bb.x, bb.y, bb.z, bb.w};

#pragma unroll
    for (int i = 0; i < 4; i++) {
        int n = row0 + (ty << 2) + i;
        float4 v;
        v.x = acc[i][0] + br4[0];
        v.y = acc[i][1] + br4[1];
        v.z = acc[i][2] + br4[2];
        v.w = acc[i][3] + br4[3];
        size_t idx;
        if (qkv_mode) {
            int b = n >> 12;                 // SEQ = 4096
            int s = n & (SEQ - 1);
            int h = blockIdx.y;              // 64 cols == one head
            idx = (((size_t)(b * NHEAD + h)) * SEQ + s) * HDIM + (tx << 2);
        } else {
            idx = (size_t)n * DMODEL + col0 + (tx << 2);
        }
        *(float4*)&out[idx] = v;
    }
}

// =================================================================
// Flash attention, fp32, causal. BQ=BK=64, 256 threads.
// grid: (SEQ/64, NHEAD, BATCH)
// SMEM (dynamic, 67584 B):
//   Qs [64][68] d-major   Ks [64][68] d-major
//   Vs [64][64] k-major   Ps [64][64] q-major
// =================================================================
#define QPAD 68
#define FLASH_SMEM_FLOATS (2*64*QPAD + 2*64*64)   // 16896
#define FLASH_SMEM_BYTES  (FLASH_SMEM_FLOATS*4)   // 67584

__global__ __launch_bounds__(256) void flash_kernel()
{
    extern __shared__ float sm[];
    float* Qs = sm;                    // [d][q] stride 68
    float* Ks = sm + 64 * QPAD;        // [d][k] stride 68
    float* Vs = sm + 2 * 64 * QPAD;    // [k][d] stride 64
    float* Ps = Vs + 64 * 64;          // [q][k] stride 64

    const int tid = threadIdx.x;
    const int ty = tid >> 4;           // q group
    const int tx = tid & 15;           // k group (S-phase) / d group (AV-phase)
    const int qt = blockIdx.x, h = blockIdx.y, b = blockIdx.z;

    const size_t base = ((size_t)(b * NHEAD + h)) * SEQ * HDIM;
    const float* Qg = g_q + base + (size_t)qt * 64 * HDIM;
    const float* Kg = g_k + base;
    const float* Vg = g_v + base;

    // load Q tile, transpose to d-major
#pragma unroll
    for (int it = 0; it < 4; it++) {
        int slot = it * 256 + tid;
        int r = slot >> 4;             // 0..63 row
        int c = (slot & 15) << 2;      // 0..60 dim
        float4 v = *(const float4*)(Qg + r * HDIM + c);
        Qs[(c + 0) * QPAD + r] = v.x;
        Qs[(c + 1) * QPAD + r] = v.y;
        Qs[(c + 2) * QPAD + r] = v.z;
        Qs[(c + 3) * QPAD + r] = v.w;
    }

    float o[4][4] = {};
    float mrow[4] = {-INFINITY, -INFINITY, -INFINITY, -INFINITY};
    float lrow[4] = {};

    const int ntiles = qt + 1;         // causal: tiles 0..qt
    for (int kt = 0; kt < ntiles; kt++) {
        __syncthreads();               // prev AV reads of Ks/Vs done
#pragma unroll
        for (int it = 0; it < 4; it++) {
            int slot = it * 256 + tid;
            int r = slot >> 4;
            int c = (slot & 15) << 2;
            float4 kv = *(const float4*)(Kg + (size_t)(kt * 64 + r) * HDIM + c);
            Ks[(c + 0) * QPAD + r] = kv.x;
            Ks[(c + 1) * QPAD + r] = kv.y;
            Ks[(c + 2) * QPAD + r] = kv.z;
            Ks[(c + 3) * QPAD + r] = kv.w;
            *(float4*)&Vs[r * 64 + c] =
                *(const float4*)(Vg + (size_t)(kt * 64 + r) * HDIM + c);
        }
        __syncthreads();

        // ---- S = Q K^T ----
        float s[4][4] = {};
#pragma unroll 16
        for (int d = 0; d < 64; d++) {
            float4 a  = *(const float4*)&Qs[d * QPAD + (ty << 2)];
            float4 bq = *(const float4*)&Ks[d * QPAD + (tx << 2)];
            float ar[4] = {a.x, a.y, a.z, a.w};
            float br[4] = {bq.x, bq.y, bq.z, bq.w};
#pragma unroll
            for (int i = 0; i < 4; i++)
#pragma unroll
                for (int j = 0; j < 4; j++)
                    s[i][j] += ar[i] * br[j];
        }

        const float scale = 0.125f;    // 1/sqrt(64)
        if (kt == qt) {
#pragma unroll
            for (int i = 0; i < 4; i++) {
                int qg = (ty << 2) + i;
#pragma unroll
                for (int j = 0; j < 4; j++) {
                    int kg = (tx << 2) + j;
                    s[i][j] = (kg > qg) ? -INFINITY : s[i][j] * scale;
                }
            }
        } else {
#pragma unroll
            for (int i = 0; i < 4; i++)
#pragma unroll
                for (int j = 0; j < 4; j++)
                    s[i][j] *= scale;
        }

        // ---- online softmax (rows span 16 lanes; xor<16 stays in half-warp) ----
#pragma unroll
        for (int i = 0; i < 4; i++) {
            float mt = fmaxf(fmaxf(s[i][0], s[i][1]), fmaxf(s[i][2], s[i][3]));
#pragma unroll
            for (int off = 8; off >= 1; off >>= 1)
                mt = fmaxf(mt, __shfl_xor_sync(0xffffffffu, mt, off));
            float mnew  = fmaxf(mrow[i], mt);
            float alpha = __expf(mrow[i] - mnew);   // first tile: exp(-inf)=0
            float p0 = __expf(s[i][0] - mnew);
            float p1 = __expf(s[i][1] - mnew);
            float p2 = __expf(s[i][2] - mnew);
            float p3 = __expf(s[i][3] - mnew);
            float rs = p0 + p1 + p2 + p3;
#pragma unroll
            for (int off = 8; off >= 1; off >>= 1)
                rs += __shfl_xor_sync(0xffffffffu, rs, off);
            lrow[i] = lrow[i] * alpha + rs;
            mrow[i] = mnew;
#pragma unroll
            for (int j = 0; j < 4; j++) o[i][j] *= alpha;  // same ty rows in AV-phase
            float4 pv; pv.x = p0; pv.y = p1; pv.z = p2; pv.w = p3;
            *(float4*)&Ps[((ty << 2) + i) * 64 + (tx << 2)] = pv;
        }
        __syncthreads();

        // ---- O += P V ----
#pragma unroll 4
        for (int k4 = 0; k4 < 64; k4 += 4) {
            float pr[4][4], vr[4][4];
#pragma unroll
            for (int i = 0; i < 4; i++) {
                float4 t = *(const float4*)&Ps[((ty << 2) + i) * 64 + k4];  // broadcast
                pr[i][0] = t.x; pr[i][1] = t.y; pr[i][2] = t.z; pr[i][3] = t.w;
            }
#pragma unroll
            for (int kk = 0; kk < 4; kk++) {
                float4 t = *(const float4*)&Vs[(k4 + kk) * 64 + (tx << 2)]; // consecutive
                vr[kk][0] = t.x; vr[kk][1] = t.y; vr[kk][2] = t.z; vr[kk][3] = t.w;
            }
#pragma unroll
            for (int i = 0; i < 4; i++)
#pragma unroll
                for (int kk = 0; kk < 4; kk++)
#pragma unroll
                    for (int j = 0; j < 4; j++)
                        o[i][j] += pr[i][kk] * vr[kk][j];
        }
    }

    // ---- epilogue: write preout [B,S,768] ----
#pragma unroll
    for (int i = 0; i < 4; i++) {
        float inv = __fdividef(1.0f, lrow[i]);
        int srow = qt * 64 + (ty << 2) + i;
        size_t idx = ((size_t)b * SEQ + srow) * DMODEL + h * HDIM + (tx << 2);
        float4 v;
        v.x = o[i][0] * inv; v.y = o[i][1] * inv;
        v.z = o[i][2] * inv; v.w = o[i][3] * inv;
        *(float4*)&g_pre[idx] = v;
    }
}

// =================================================================
extern "C" void kernel_launch(void* const* d_in, const int* in_sizes, int n_in,
                              void* d_out, int out_size)
{
    (void)in_sizes; (void)n_in; (void)out_size;
    const float* x  = (const float*)d_in[0];
    const float* Wq = (const float*)d_in[1];
    const float* bq = (const float*)d_in[2];
    const float* Wk = (const float*)d_in[3];
    const float* bk = (const float*)d_in[4];
    const float* Wv = (const float*)d_in[5];
    const float* bv = (const float*)d_in[6];
    const float* Wo = (const float*)d_in[7];
    const float* bo = (const float*)d_in[8];
    float* out = (float*)d_out;

    void *pq, *pk, *pv, *ppre;
    cudaGetSymbolAddress(&pq, g_q);
    cudaGetSymbolAddress(&pk, g_k);
    cudaGetSymbolAddress(&pv, g_v);
    cudaGetSymbolAddress(&ppre, g_pre);

    // immediate (non-stream) API: capture-safe; also runs in the uncaptured
    // correctness call first, so the attribute is set before capture anyway.
    cudaFuncSetAttribute(flash_kernel,
                         cudaFuncAttributeMaxDynamicSharedMemorySize,
                         FLASH_SMEM_BYTES);

    dim3 gg(NTOK / 64, DMODEL / 64);   // 128 x 12
    gemm64_kernel<<<gg, 256>>>(x, Wq, bq, (float*)pq, 1);
    gemm64_kernel<<<gg, 256>>>(x, Wk, bk, (float*)pk, 1);
    gemm64_kernel<<<gg, 256>>>(x, Wv, bv, (float*)pv, 1);

    dim3 gf(SEQ / 64, NHEAD, BATCH);   // 64 x 12 x 2
    flash_kernel<<<gf, 256, FLASH_SMEM_BYTES>>>();

    gemm64_kernel<<<gg, 256>>>((const float*)ppre, Wo, bo, out, 0);
}

// round 6
// speedup vs baseline: 1.3186x; 1.3186x over previous
#include <cuda_runtime.h>
#include <cuda_bf16.h>
#include <math.h>
#include <stdint.h>

#define BATCH 2
#define SEQ   4096
#define DMODEL 768
#define NHEAD 12
#define HDIM  64
#define NTOK  (BATCH*SEQ)   // 8192

// ---------------- scratch (no allocations allowed) ----------------
__device__ float g_q[(size_t)BATCH*NHEAD*SEQ*HDIM];    // [B,H,S,64]
__device__ float g_k[(size_t)BATCH*NHEAD*SEQ*HDIM];
__device__ float g_v[(size_t)BATCH*NHEAD*SEQ*HDIM];
__device__ float g_pre[(size_t)NTOK*DMODEL];           // [B,S,768]

__device__ __nv_bfloat16 g_xhi[(size_t)NTOK*DMODEL];   // splits of x (reused for pre)
__device__ __nv_bfloat16 g_xlo[(size_t)NTOK*DMODEL];
__device__ __nv_bfloat16 g_whi[4*(size_t)DMODEL*DMODEL];
__device__ __nv_bfloat16 g_wlo[4*(size_t)DMODEL*DMODEL];

// ================= portable (sm_80+) asm helpers =================
__device__ __forceinline__ uint32_t smem_u32(const void* p){
    uint32_t a;
    asm("{ .reg .u64 t; cvta.to.shared.u64 t, %1; cvt.u32.u64 %0, t; }" : "=r"(a) : "l"(p));
    return a;
}

#define CP_ASYNC16(dst, src) \
    asm volatile("cp.async.cg.shared.global [%0], [%1], 16;" :: "r"(dst), "l"(src))
#define CP_COMMIT()  asm volatile("cp.async.commit_group;" ::: "memory")
#define CP_WAIT0()   asm volatile("cp.async.wait_group 0;" ::: "memory")

#define LDSM4(r, addr) \
    asm volatile("ldmatrix.sync.aligned.m8n8.x4.shared.b16 {%0,%1,%2,%3}, [%4];" \
        : "=r"((r)[0]), "=r"((r)[1]), "=r"((r)[2]), "=r"((r)[3]) : "r"(addr))

#define MMA_BF16(d, a, b0, b1) \
    asm volatile("mma.sync.aligned.m16n8k16.row.col.f32.bf16.bf16.f32 " \
        "{%0,%1,%2,%3}, {%4,%5,%6,%7}, {%8,%9}, {%0,%1,%2,%3};" \
        : "+f"((d)[0]), "+f"((d)[1]), "+f"((d)[2]), "+f"((d)[3]) \
        : "r"((a)[0]), "r"((a)[1]), "r"((a)[2]), "r"((a)[3]), "r"(b0), "r"(b1))

// =================================================================
// split kernel: v -> (hi, lo) bf16 pair, hi = bf16(v), lo = bf16(v-hi)
// =================================================================
__global__ void split_kernel(const float* __restrict__ in,
                             __nv_bfloat16* __restrict__ hi,
                             __nv_bfloat16* __restrict__ lo, int n4)
{
    int i = blockIdx.x * blockDim.x + threadIdx.x;
    if (i >= n4) return;
    float4 v = ((const float4*)in)[i];
    __nv_bfloat16 h0 = __float2bfloat16(v.x);
    __nv_bfloat16 h1 = __float2bfloat16(v.y);
    __nv_bfloat16 h2 = __float2bfloat16(v.z);
    __nv_bfloat16 h3 = __float2bfloat16(v.w);
    __nv_bfloat16 l0 = __float2bfloat16(v.x - __bfloat162float(h0));
    __nv_bfloat16 l1 = __float2bfloat16(v.y - __bfloat162float(h1));
    __nv_bfloat16 l2 = __float2bfloat16(v.z - __bfloat162float(h2));
    __nv_bfloat16 l3 = __float2bfloat16(v.w - __bfloat162float(h3));
    __nv_bfloat162 hp0; hp0.x = h0; hp0.y = h1;
    __nv_bfloat162 hp1; hp1.x = h2; hp1.y = h3;
    __nv_bfloat162 lp0; lp0.x = l0; lp0.y = l1;
    __nv_bfloat162 lp1; lp1.x = l2; lp1.y = l3;
    ((__nv_bfloat162*)hi)[2*i]   = hp0;
    ((__nv_bfloat162*)hi)[2*i+1] = hp1;
    ((__nv_bfloat162*)lo)[2*i]   = lp0;
    ((__nv_bfloat162*)lo)[2*i+1] = lp1;
}

// =================================================================
// mma.sync split-bf16 GEMM: out = X @ W^T + bias
// X: [NTOK,768] (hi/lo bf16), W: [768,768] row-major W[o][k] (hi/lo)
// CTA tile 128x64, 8 warps (4m x 2n), warp tile 32x32.
// K-chunks of 64; SMEM rows padded to 144B -> conflict-free ldmatrix.
// =================================================================
#define GKC 64
#define NKCH (DMODEL/GKC)          // 12
#define APITCH_B 144               // bytes per smem row (64 bf16 + 8 pad)

#define SA_HI 0
#define SA_LO 18432                // 128*144
#define SB_HI 36864
#define SB_LO 46080                // + 64*144
#define GEMM_SMEM 55296

__global__ __launch_bounds__(256, 2) void mma_gemm_kernel(
    const __nv_bfloat16* __restrict__ Xhi, const __nv_bfloat16* __restrict__ Xlo,
    const __nv_bfloat16* __restrict__ Whi, const __nv_bfloat16* __restrict__ Wlo,
    const float* __restrict__ bias, float* __restrict__ out, int qkv_mode)
{
    extern __shared__ char smem[];
    const uint32_t sb = smem_u32(smem);
    const int tid  = threadIdx.x;
    const int wid  = tid >> 5, lane = tid & 31;
    const int wm   = wid >> 1;          // 0..3  (m: 32 rows each)
    const int wn   = wid & 1;           // 0..1  (n: 32 cols each)
    const int row0 = blockIdx.x * 128;
    const int col0 = blockIdx.y * 64;

    float acc[2][4][4] = {};            // [mf][nf][d0..d3]

    for (int ck = 0; ck < NKCH; ck++) {
        const int k0 = ck * GKC;
        if (ck) __syncthreads();        // all warps done reading smem

        // ---- load A (128x64) hi+lo : 4 iters of 256 granules each buf ----
#pragma unroll
        for (int it = 0; it < 4; it++) {
            int g = it * 256 + tid;     // 0..1023
            int r = g >> 3, c = g & 7;
            uint32_t soff = (uint32_t)(r * APITCH_B + c * 16);
            size_t goff = (size_t)(row0 + r) * DMODEL + k0 + c * 8;
            CP_ASYNC16(sb + SA_HI + soff, Xhi + goff);
            CP_ASYNC16(sb + SA_LO + soff, Xlo + goff);
        }
        // ---- load B (64x64) hi+lo : 2 iters ----
#pragma unroll
        for (int it = 0; it < 2; it++) {
            int g = it * 256 + tid;     // 0..511
            int r = g >> 3, c = g & 7;
            uint32_t soff = (uint32_t)(r * APITCH_B + c * 16);
            size_t goff = (size_t)(col0 + r) * DMODEL + k0 + c * 8;
            CP_ASYNC16(sb + SB_HI + soff, Whi + goff);
            CP_ASYNC16(sb + SB_LO + soff, Wlo + goff);
        }
        CP_COMMIT();
        CP_WAIT0();
        __syncthreads();

        // ---- compute: 4 k16 steps ----
#pragma unroll
        for (int s = 0; s < 4; s++) {
            const int kk = s * 16;
            uint32_t ah[2][4], al[2][4], bh[2][4], bl[2][4];
#pragma unroll
            for (int mf = 0; mf < 2; mf++) {
                int arow = wm * 32 + mf * 16 + (lane & 15);
                uint32_t off = (uint32_t)(arow * APITCH_B + (kk + ((lane >> 4) << 3)) * 2);
                LDSM4(ah[mf], sb + SA_HI + off);
                LDSM4(al[mf], sb + SA_LO + off);
            }
#pragma unroll
            for (int q = 0; q < 2; q++) {
                int brow = wn * 32 + q * 16 + ((lane >> 4) << 3) + (lane & 7);
                uint32_t off = (uint32_t)(brow * APITCH_B + (kk + (((lane >> 3) & 1) << 3)) * 2);
                LDSM4(bh[q], sb + SB_HI + off);
                LDSM4(bl[q], sb + SB_LO + off);
            }
#pragma unroll
            for (int mf = 0; mf < 2; mf++)
#pragma unroll
                for (int nf = 0; nf < 4; nf++) {
                    int q = nf >> 1, p = (nf & 1) << 1;
                    MMA_BF16(acc[mf][nf], ah[mf], bh[q][p], bh[q][p+1]);  // hi*hi
                    MMA_BF16(acc[mf][nf], ah[mf], bl[q][p], bl[q][p+1]);  // hi*lo
                    MMA_BF16(acc[mf][nf], al[mf], bh[q][p], bh[q][p+1]);  // lo*hi
                }
        }
    }

    // ---- epilogue: bias + scatter ----
#pragma unroll
    for (int mf = 0; mf < 2; mf++)
#pragma unroll
        for (int nf = 0; nf < 4; nf++) {
            int colh = wn * 32 + nf * 8 + ((lane & 3) << 1);   // 0..62 in 64-tile
            int col  = col0 + colh;
            float2 bb = *(const float2*)&bias[col];
#pragma unroll
            for (int hr = 0; hr < 2; hr++) {
                int n = row0 + wm * 32 + mf * 16 + (lane >> 2) + hr * 8;
                float2 v;
                v.x = acc[mf][nf][hr*2+0] + bb.x;
                v.y = acc[mf][nf][hr*2+1] + bb.y;
                size_t idx;
                if (qkv_mode) {
                    int b = n >> 12, sq = n & (SEQ - 1);
                    idx = (((size_t)(b * NHEAD + blockIdx.y)) * SEQ + sq) * HDIM + colh;
                } else {
                    idx = (size_t)n * DMODEL + col;
                }
                *(float2*)&out[idx] = v;
            }
        }
}

// =================================================================
// Flash attention, fp32, causal. BQ=BK=64, 256 threads. (unchanged)
// =================================================================
#define QPAD 68
#define FLASH_SMEM_FLOATS (2*64*QPAD + 2*64*64)   // 16896
#define FLASH_SMEM_BYTES  (FLASH_SMEM_FLOATS*4)   // 67584

__global__ __launch_bounds__(256) void flash_kernel()
{
    extern __shared__ float sm[];
    float* Qs = sm;                    // [d][q] stride 68
    float* Ks = sm + 64 * QPAD;        // [d][k] stride 68
    float* Vs = sm + 2 * 64 * QPAD;    // [k][d] stride 64
    float* Ps = Vs + 64 * 64;          // [q][k] stride 64

    const int tid = threadIdx.x;
    const int ty = tid >> 4;
    const int tx = tid & 15;
    const int qt = blockIdx.x, h = blockIdx.y, b = blockIdx.z;

    const size_t base = ((size_t)(b * NHEAD + h)) * SEQ * HDIM;
    const float* Qg = g_q + base + (size_t)qt * 64 * HDIM;
    const float* Kg = g_k + base;
    const float* Vg = g_v + base;

#pragma unroll
    for (int it = 0; it < 4; it++) {
        int slot = it * 256 + tid;
        int r = slot >> 4;
        int c = (slot & 15) << 2;
        float4 v = *(const float4*)(Qg + r * HDIM + c);
        Qs[(c + 0) * QPAD + r] = v.x;
        Qs[(c + 1) * QPAD + r] = v.y;
        Qs[(c + 2) * QPAD + r] = v.z;
        Qs[(c + 3) * QPAD + r] = v.w;
    }

    float o[4][4] = {};
    float mrow[4] = {-INFINITY, -INFINITY, -INFINITY, -INFINITY};
    float lrow[4] = {};

    const int ntiles = qt + 1;
    for (int kt = 0; kt < ntiles; kt++) {
        __syncthreads();
#pragma unroll
        for (int it = 0; it < 4; it++) {
            int slot = it * 256 + tid;
            int r = slot >> 4;
            int c = (slot & 15) << 2;
            float4 kv = *(const float4*)(Kg + (size_t)(kt * 64 + r) * HDIM + c);
            Ks[(c + 0) * QPAD + r] = kv.x;
            Ks[(c + 1) * QPAD + r] = kv.y;
            Ks[(c + 2) * QPAD + r] = kv.z;
            Ks[(c + 3) * QPAD + r] = kv.w;
            *(float4*)&Vs[r * 64 + c] =
                *(const float4*)(Vg + (size_t)(kt * 64 + r) * HDIM + c);
        }
        __syncthreads();

        float s[4][4] = {};
#pragma unroll 16
        for (int d = 0; d < 64; d++) {
            float4 a  = *(const float4*)&Qs[d * QPAD + (ty << 2)];
            float4 bq = *(const float4*)&Ks[d * QPAD + (tx << 2)];
            float ar[4] = {a.x, a.y, a.z, a.w};
            float br[4] = {bq.x, bq.y, bq.z, bq.w};
#pragma unroll
            for (int i = 0; i < 4; i++)
#pragma unroll
                for (int j = 0; j < 4; j++)
                    s[i][j] += ar[i] * br[j];
        }

        const float scale = 0.125f;
        if (kt == qt) {
#pragma unroll
            for (int i = 0; i < 4; i++) {
                int qg = (ty << 2) + i;
#pragma unroll
                for (int j = 0; j < 4; j++) {
                    int kg = (tx << 2) + j;
                    s[i][j] = (kg > qg) ? -INFINITY : s[i][j] * scale;
                }
            }
        } else {
#pragma unroll
            for (int i = 0; i < 4; i++)
#pragma unroll
                for (int j = 0; j < 4; j++)
                    s[i][j] *= scale;
        }

#pragma unroll
        for (int i = 0; i < 4; i++) {
            float mt = fmaxf(fmaxf(s[i][0], s[i][1]), fmaxf(s[i][2], s[i][3]));
#pragma unroll
            for (int off = 8; off >= 1; off >>= 1)
                mt = fmaxf(mt, __shfl_xor_sync(0xffffffffu, mt, off));
            float mnew  = fmaxf(mrow[i], mt);
            float alpha = __expf(mrow[i] - mnew);
            float p0 = __expf(s[i][0] - mnew);
            float p1 = __expf(s[i][1] - mnew);
            float p2 = __expf(s[i][2] - mnew);
            float p3 = __expf(s[i][3] - mnew);
            float rs = p0 + p1 + p2 + p3;
#pragma unroll
            for (int off = 8; off >= 1; off >>= 1)
                rs += __shfl_xor_sync(0xffffffffu, rs, off);
            lrow[i] = lrow[i] * alpha + rs;
            mrow[i] = mnew;
#pragma unroll
            for (int j = 0; j < 4; j++) o[i][j] *= alpha;
            float4 pv; pv.x = p0; pv.y = p1; pv.z = p2; pv.w = p3;
            *(float4*)&Ps[((ty << 2) + i) * 64 + (tx << 2)] = pv;
        }
        __syncthreads();

#pragma unroll 4
        for (int k4 = 0; k4 < 64; k4 += 4) {
            float pr[4][4], vr[4][4];
#pragma unroll
            for (int i = 0; i < 4; i++) {
                float4 t = *(const float4*)&Ps[((ty << 2) + i) * 64 + k4];
                pr[i][0] = t.x; pr[i][1] = t.y; pr[i][2] = t.z; pr[i][3] = t.w;
            }
#pragma unroll
            for (int kk = 0; kk < 4; kk++) {
                float4 t = *(const float4*)&Vs[(k4 + kk) * 64 + (tx << 2)];
                vr[kk][0] = t.x; vr[kk][1] = t.y; vr[kk][2] = t.z; vr[kk][3] = t.w;
            }
#pragma unroll
            for (int i = 0; i < 4; i++)
#pragma unroll
                for (int kk = 0; kk < 4; kk++)
#pragma unroll
                    for (int j = 0; j < 4; j++)
                        o[i][j] += pr[i][kk] * vr[kk][j];
        }
    }

#pragma unroll
    for (int i = 0; i < 4; i++) {
        float inv = __fdividef(1.0f, lrow[i]);
        int srow = qt * 64 + (ty << 2) + i;
        size_t idx = ((size_t)b * SEQ + srow) * DMODEL + h * HDIM + (tx << 2);
        float4 v;
        v.x = o[i][0] * inv; v.y = o[i][1] * inv;
        v.z = o[i][2] * inv; v.w = o[i][3] * inv;
        *(float4*)&g_pre[idx] = v;
    }
}

// =================================================================
extern "C" void kernel_launch(void* const* d_in, const int* in_sizes, int n_in,
                              void* d_out, int out_size)
{
    (void)in_sizes; (void)n_in; (void)out_size;
    const float* x  = (const float*)d_in[0];
    const float* Wq = (const float*)d_in[1];
    const float* bq = (const float*)d_in[2];
    const float* Wk = (const float*)d_in[3];
    const float* bk = (const float*)d_in[4];
    const float* Wv = (const float*)d_in[5];
    const float* bv = (const float*)d_in[6];
    const float* Wo = (const float*)d_in[7];
    const float* bo = (const float*)d_in[8];
    float* out = (float*)d_out;

    void *pq, *pk, *pv, *ppre, *pxh, *pxl, *pwh, *pwl;
    cudaGetSymbolAddress(&pq,  g_q);
    cudaGetSymbolAddress(&pk,  g_k);
    cudaGetSymbolAddress(&pv,  g_v);
    cudaGetSymbolAddress(&ppre, g_pre);
    cudaGetSymbolAddress(&pxh, g_xhi);
    cudaGetSymbolAddress(&pxl, g_xlo);
    cudaGetSymbolAddress(&pwh, g_whi);
    cudaGetSymbolAddress(&pwl, g_wlo);

    __nv_bfloat16* xhi = (__nv_bfloat16*)pxh;
    __nv_bfloat16* xlo = (__nv_bfloat16*)pxl;
    __nv_bfloat16* whi = (__nv_bfloat16*)pwh;
    __nv_bfloat16* wlo = (__nv_bfloat16*)pwl;
    const size_t WSZ = (size_t)DMODEL * DMODEL;   // 589824

    cudaFuncSetAttribute(flash_kernel,
                         cudaFuncAttributeMaxDynamicSharedMemorySize, FLASH_SMEM_BYTES);
    cudaFuncSetAttribute(mma_gemm_kernel,
                         cudaFuncAttributeMaxDynamicSharedMemorySize, GEMM_SMEM);

    // ---- split conversions ----
    const int XN4 = NTOK * DMODEL / 4;     // 1572864
    const int WN4 = (int)(WSZ / 4);        // 147456
    split_kernel<<<XN4 / 256, 256>>>(x,  xhi, xlo, XN4);
    split_kernel<<<WN4 / 256, 256>>>(Wq, whi + 0*WSZ, wlo + 0*WSZ, WN4);
    split_kernel<<<WN4 / 256, 256>>>(Wk, whi + 1*WSZ, wlo + 1*WSZ, WN4);
    split_kernel<<<WN4 / 256, 256>>>(Wv, whi + 2*WSZ, wlo + 2*WSZ, WN4);
    split_kernel<<<WN4 / 256, 256>>>(Wo, whi + 3*WSZ, wlo + 3*WSZ, WN4);

    // ---- QKV projections on mma.sync ----
    dim3 gg(NTOK / 128, DMODEL / 64);      // 64 x 12
    mma_gemm_kernel<<<gg, 256, GEMM_SMEM>>>(xhi, xlo, whi + 0*WSZ, wlo + 0*WSZ, bq, (float*)pq, 1);
    mma_gemm_kernel<<<gg, 256, GEMM_SMEM>>>(xhi, xlo, whi + 1*WSZ, wlo + 1*WSZ, bk, (float*)pk, 1);
    mma_gemm_kernel<<<gg, 256, GEMM_SMEM>>>(xhi, xlo, whi + 2*WSZ, wlo + 2*WSZ, bv, (float*)pv, 1);

    // ---- attention ----
    dim3 gf(SEQ / 64, NHEAD, BATCH);       // 64 x 12 x 2
    flash_kernel<<<gf, 256, FLASH_SMEM_BYTES>>>();

    // ---- output projection ----
    split_kernel<<<XN4 / 256, 256>>>((const float*)ppre, xhi, xlo, XN4);
    mma_gemm_kernel<<<gg, 256, GEMM_SMEM>>>(xhi, xlo, whi + 3*WSZ, wlo + 3*WSZ, bo, out, 0);
}

// round 8
// speedup vs baseline: 2.3938x; 1.8154x over previous
#include <cuda_runtime.h>
#include <cuda_bf16.h>
#include <math.h>
#include <stdint.h>

#define BATCH 2
#define SEQ   4096
#define DMODEL 768
#define NHEAD 12
#define HDIM  64
#define NTOK  (BATCH*SEQ)   // 8192

// ---------------- scratch (no allocations allowed) ----------------
__device__ __nv_bfloat16 g_qhi[(size_t)BATCH*NHEAD*SEQ*HDIM];  // [B,H,S,64], pre-scaled 1/8
__device__ __nv_bfloat16 g_qlo[(size_t)BATCH*NHEAD*SEQ*HDIM];
__device__ __nv_bfloat16 g_khi[(size_t)BATCH*NHEAD*SEQ*HDIM];
__device__ __nv_bfloat16 g_klo[(size_t)BATCH*NHEAD*SEQ*HDIM];
__device__ __nv_bfloat16 g_vhi[(size_t)BATCH*NHEAD*SEQ*HDIM];
__device__ __nv_bfloat16 g_vlo[(size_t)BATCH*NHEAD*SEQ*HDIM];

__device__ __nv_bfloat16 g_xhi[(size_t)NTOK*DMODEL];   // x splits; later reused for preout splits
__device__ __nv_bfloat16 g_xlo[(size_t)NTOK*DMODEL];
__device__ __nv_bfloat16 g_whi[4*(size_t)DMODEL*DMODEL];
__device__ __nv_bfloat16 g_wlo[4*(size_t)DMODEL*DMODEL];

// ================= portable (sm_80+) asm helpers =================
__device__ __forceinline__ uint32_t smem_u32(const void* p){
    uint32_t a;
    asm("{ .reg .u64 t; cvta.to.shared.u64 t, %1; cvt.u32.u64 %0, t; }" : "=r"(a) : "l"(p));
    return a;
}

#define CP_ASYNC16(dst, src) \
    asm volatile("cp.async.cg.shared.global [%0], [%1], 16;" :: "r"(dst), "l"(src))
#define CP_COMMIT()  asm volatile("cp.async.commit_group;" ::: "memory")
#define CP_WAIT0()   asm volatile("cp.async.wait_group 0;" ::: "memory")

#define LDSM4(r, addr) \
    asm volatile("ldmatrix.sync.aligned.m8n8.x4.shared.b16 {%0,%1,%2,%3}, [%4];" \
        : "=r"((r)[0]), "=r"((r)[1]), "=r"((r)[2]), "=r"((r)[3]) : "r"(addr))

#define LDSM4T(r, addr) \
    asm volatile("ldmatrix.sync.aligned.m8n8.x4.trans.shared.b16 {%0,%1,%2,%3}, [%4];" \
        : "=r"((r)[0]), "=r"((r)[1]), "=r"((r)[2]), "=r"((r)[3]) : "r"(addr))

#define MMA_BF16(d, a, b0, b1) \
    asm volatile("mma.sync.aligned.m16n8k16.row.col.f32.bf16.bf16.f32 " \
        "{%0,%1,%2,%3}, {%4,%5,%6,%7}, {%8,%9}, {%0,%1,%2,%3};" \
        : "+f"((d)[0]), "+f"((d)[1]), "+f"((d)[2]), "+f"((d)[3]) \
        : "r"((a)[0]), "r"((a)[1]), "r"((a)[2]), "r"((a)[3]), "r"(b0), "r"(b1))

// pack two f32 into bf16x2: lo half = first arg, hi half = second
__device__ __forceinline__ uint32_t packbf(float lo, float hi){
    uint32_t r;
    asm("cvt.rn.bf16x2.f32 %0, %1, %2;" : "=r"(r) : "f"(hi), "f"(lo));
    return r;
}
__device__ __forceinline__ float lo16f(uint32_t p){ return __uint_as_float(p << 16); }
__device__ __forceinline__ float hi16f(uint32_t p){ return __uint_as_float(p & 0xffff0000u); }

// fast exp on fma/alu pipes (avoids MUFU throughput wall).
// t <= 0 expected; clamp makes -1e30 sentinel -> ~0. Rel err ~2.4e-6.
__device__ __forceinline__ float expapx(float t){
    t = fmaxf(t, -80.f);
    float z = t * 1.4426950408889634f;
    float n = rintf(z);
    float u = fmaf(n, -0.69314718056f, t);
    float p = 0.008333333f;
    p = fmaf(p, u, 0.041666667f);
    p = fmaf(p, u, 0.166666667f);
    p = fmaf(p, u, 0.5f);
    p = fmaf(p, u, 1.0f);
    p = fmaf(p, u, 1.0f);
    int ei = ((int)n + 127) << 23;
    return p * __int_as_float(ei);
}

// =================================================================
// split kernel: v -> (hi, lo) bf16 pair
// =================================================================
__global__ void split_kernel(const float* __restrict__ in,
                             __nv_bfloat16* __restrict__ hi,
                             __nv_bfloat16* __restrict__ lo, int n4)
{
    int i = blockIdx.x * blockDim.x + threadIdx.x;
    if (i >= n4) return;
    float4 v = ((const float4*)in)[i];
    uint32_t h0 = packbf(v.x, v.y);
    uint32_t h1 = packbf(v.z, v.w);
    uint32_t l0 = packbf(v.x - lo16f(h0), v.y - hi16f(h0));
    uint32_t l1 = packbf(v.z - lo16f(h1), v.w - hi16f(h1));
    ((uint32_t*)hi)[2*i]   = h0;
    ((uint32_t*)hi)[2*i+1] = h1;
    ((uint32_t*)lo)[2*i]   = l0;
    ((uint32_t*)lo)[2*i+1] = l1;
}

// =================================================================
// mma.sync split-bf16 GEMM: out = X @ W^T + bias
// mode 0: f32 out [NTOK,768].  mode 1: bf16 hi/lo split, head-major
// [B,H,S,64] (block col tile == head), value scaled by `scale`.
// =================================================================
#define GKC 64
#define NKCH (DMODEL/GKC)          // 12
#define APITCH_B 144

#define SA_HI 0
#define SA_LO 18432
#define SB_HI 36864
#define SB_LO 46080
#define GEMM_SMEM 55296

__global__ __launch_bounds__(256, 2) void mma_gemm_kernel(
    const __nv_bfloat16* __restrict__ Xhi, const __nv_bfloat16* __restrict__ Xlo,
    const __nv_bfloat16* __restrict__ Whi, const __nv_bfloat16* __restrict__ Wlo,
    const float* __restrict__ bias, float* __restrict__ outF,
    __nv_bfloat16* __restrict__ outHi, __nv_bfloat16* __restrict__ outLo,
    int mode, float scale)
{
    extern __shared__ char smem[];
    const uint32_t sb = smem_u32(smem);
    const int tid  = threadIdx.x;
    const int wid  = tid >> 5, lane = tid & 31;
    const int wm   = wid >> 1;
    const int wn   = wid & 1;
    const int row0 = blockIdx.x * 128;
    const int col0 = blockIdx.y * 64;

    float acc[2][4][4] = {};

    for (int ck = 0; ck < NKCH; ck++) {
        const int k0 = ck * GKC;
        if (ck) __syncthreads();

#pragma unroll
        for (int it = 0; it < 4; it++) {
            int g = it * 256 + tid;
            int r = g >> 3, c = g & 7;
            uint32_t soff = (uint32_t)(r * APITCH_B + c * 16);
            size_t goff = (size_t)(row0 + r) * DMODEL + k0 + c * 8;
            CP_ASYNC16(sb + SA_HI + soff, Xhi + goff);
            CP_ASYNC16(sb + SA_LO + soff, Xlo + goff);
        }
#pragma unroll
        for (int it = 0; it < 2; it++) {
            int g = it * 256 + tid;
            int r = g >> 3, c = g & 7;
            uint32_t soff = (uint32_t)(r * APITCH_B + c * 16);
            size_t goff = (size_t)(col0 + r) * DMODEL + k0 + c * 8;
            CP_ASYNC16(sb + SB_HI + soff, Whi + goff);
            CP_ASYNC16(sb + SB_LO + soff, Wlo + goff);
        }
        CP_COMMIT();
        CP_WAIT0();
        __syncthreads();

#pragma unroll
        for (int s = 0; s < 4; s++) {
            const int kk = s * 16;
            uint32_t ah[2][4], al[2][4], bh[2][4], bl[2][4];
#pragma unroll
            for (int mf = 0; mf < 2; mf++) {
                int arow = wm * 32 + mf * 16 + (lane & 15);
                uint32_t off = (uint32_t)(arow * APITCH_B + (kk + ((lane >> 4) << 3)) * 2);
                LDSM4(ah[mf], sb + SA_HI + off);
                LDSM4(al[mf], sb + SA_LO + off);
            }
#pragma unroll
            for (int q = 0; q < 2; q++) {
                int brow = wn * 32 + q * 16 + ((lane >> 4) << 3) + (lane & 7);
                uint32_t off = (uint32_t)(brow * APITCH_B + (kk + (((lane >> 3) & 1) << 3)) * 2);
                LDSM4(bh[q], sb + SB_HI + off);
                LDSM4(bl[q], sb + SB_LO + off);
            }
#pragma unroll
            for (int mf = 0; mf < 2; mf++)
#pragma unroll
                for (int nf = 0; nf < 4; nf++) {
                    int q = nf >> 1, p = (nf & 1) << 1;
                    MMA_BF16(acc[mf][nf], ah[mf], bh[q][p], bh[q][p+1]);
                    MMA_BF16(acc[mf][nf], ah[mf], bl[q][p], bl[q][p+1]);
                    MMA_BF16(acc[mf][nf], al[mf], bh[q][p], bh[q][p+1]);
                }
        }
    }

    // ---- epilogue ----
#pragma unroll
    for (int mf = 0; mf < 2; mf++)
#pragma unroll
        for (int nf = 0; nf < 4; nf++) {
            int colh = wn * 32 + nf * 8 + ((lane & 3) << 1);
            int col  = col0 + colh;
            float2 bb = *(const float2*)&bias[col];
#pragma unroll
            for (int hr = 0; hr < 2; hr++) {
                int n = row0 + wm * 32 + mf * 16 + (lane >> 2) + hr * 8;
                float vx = acc[mf][nf][hr*2+0] + bb.x;
                float vy = acc[mf][nf][hr*2+1] + bb.y;
                if (mode) {
                    vx *= scale; vy *= scale;
                    int b = n >> 12, sq = n & (SEQ - 1);
                    size_t idx = (((size_t)(b * NHEAD + blockIdx.y)) * SEQ + sq) * HDIM + colh;
                    uint32_t hp = packbf(vx, vy);
                    uint32_t lp = packbf(vx - lo16f(hp), vy - hi16f(hp));
                    *(uint32_t*)&outHi[idx] = hp;
                    *(uint32_t*)&outLo[idx] = lp;
                } else {
                    float2 v; v.x = vx; v.y = vy;
                    *(float2*)&outF[(size_t)n * DMODEL + col] = v;
                }
            }
        }
}

// =================================================================
// Tensor-core flash attention, causal. BQ=128, BK=64, 8 warps.
// Warp w owns rows [128*qt + 16w, +16). Split-bf16 3-MMA for both
// S=QK^T and O+=PV. Q pre-scaled by 1/8 at projection time.
// Writes preout directly as bf16 hi/lo splits into g_xhi/g_xlo.
// =================================================================
__global__ __launch_bounds__(256) void flash_tc_kernel()
{
    __shared__ __align__(128) unsigned char fsm[36864];
    const uint32_t sb = smem_u32(fsm);
    const int tid = threadIdx.x;
    const int warp = tid >> 5, lane = tid & 31;
    const int qt = blockIdx.x, h = blockIdx.y, b = blockIdx.z;
    const size_t bh = (size_t)(b * NHEAD + h) * SEQ;
    const int q0 = qt * 128;

    // ---- stage Q tile (hi rows 0..127 at pitch 144; lo at +18432) ----
#pragma unroll
    for (int it = 0; it < 4; it++) {
        int g = it * 256 + tid;
        int r = g >> 3, c = g & 7;
        size_t src = (bh + q0 + r) * 64 + c * 8;
        uint32_t dst = sb + r * 144 + c * 16;
        CP_ASYNC16(dst,         g_qhi + src);
        CP_ASYNC16(dst + 18432, g_qlo + src);
    }
    CP_COMMIT(); CP_WAIT0(); __syncthreads();

    uint32_t qh[4][4], ql[4][4];
    {
        int qr = warp * 16 + (lane & 15);
#pragma unroll
        for (int s = 0; s < 4; s++) {
            uint32_t off = (uint32_t)(qr * 144 + (s * 16 + ((lane >> 4) << 3)) * 2);
            LDSM4(qh[s], sb + off);
            LDSM4(ql[s], sb + 18432 + off);
        }
    }
    __syncthreads();

    float O[8][4] = {};
    float mA = -1e30f, mB = -1e30f, lA = 0.f, lB = 0.f;

    const int nkt = 2 * qt + 2;
    for (int kt = 0; kt < nkt; kt++) {
        const int key0 = kt * 64;
        // ---- load K (hi/lo) and V (hi/lo) tiles [64 keys][64] ----
#pragma unroll
        for (int it = 0; it < 2; it++) {
            int g = it * 256 + tid;
            int r = g >> 3, c = g & 7;
            size_t src = (bh + key0 + r) * 64 + c * 8;
            uint32_t dst = sb + r * 144 + c * 16;
            CP_ASYNC16(dst,         g_khi + src);
            CP_ASYNC16(dst +  9216, g_klo + src);
            CP_ASYNC16(dst + 18432, g_vhi + src);
            CP_ASYNC16(dst + 27648, g_vlo + src);
        }
        CP_COMMIT(); CP_WAIT0(); __syncthreads();

        // ---- S = (Q/8) K^T ----
        float sacc[8][4] = {};
#pragma unroll
        for (int s = 0; s < 4; s++) {
            uint32_t kbh[4][4], kbl[4][4];
#pragma unroll
            for (int t = 0; t < 4; t++) {
                uint32_t off = (uint32_t)((t * 16 + ((lane >> 4) << 3) + (lane & 7)) * 144
                             + (s * 16 + (((lane >> 3) & 1) << 3)) * 2);
                LDSM4(kbh[t], sb + off);
                LDSM4(kbl[t], sb + 9216 + off);
            }
#pragma unroll
            for (int f = 0; f < 8; f++) {
                int t = f >> 1, p = (f & 1) << 1;
                MMA_BF16(sacc[f], qh[s], kbh[t][p], kbh[t][p+1]);
                MMA_BF16(sacc[f], qh[s], kbl[t][p], kbl[t][p+1]);
                MMA_BF16(sacc[f], ql[s], kbh[t][p], kbh[t][p+1]);
            }
        }

        // ---- causal mask (only diagonal tiles) ----
        if (kt >= 2 * qt) {
            int rA = q0 + warp * 16 + (lane >> 2);
#pragma unroll
            for (int f = 0; f < 8; f++) {
                int cb = key0 + f * 8 + ((lane & 3) << 1);
                if (cb     > rA    ) sacc[f][0] = -1e30f;
                if (cb + 1 > rA    ) sacc[f][1] = -1e30f;
                if (cb     > rA + 8) sacc[f][2] = -1e30f;
                if (cb + 1 > rA + 8) sacc[f][3] = -1e30f;
            }
        }

        // ---- online softmax (rows live in quads: xor 1,2) ----
        float mtA = -1e30f, mtB = -1e30f;
#pragma unroll
        for (int f = 0; f < 8; f++) {
            mtA = fmaxf(mtA, fmaxf(sacc[f][0], sacc[f][1]));
            mtB = fmaxf(mtB, fmaxf(sacc[f][2], sacc[f][3]));
        }
        mtA = fmaxf(mtA, __shfl_xor_sync(0xffffffffu, mtA, 1));
        mtA = fmaxf(mtA, __shfl_xor_sync(0xffffffffu, mtA, 2));
        mtB = fmaxf(mtB, __shfl_xor_sync(0xffffffffu, mtB, 1));
        mtB = fmaxf(mtB, __shfl_xor_sync(0xffffffffu, mtB, 2));
        float mnA = fmaxf(mA, mtA), mnB = fmaxf(mB, mtB);
        float aA = expapx(mA - mnA), aB = expapx(mB - mnB);
        float rsA = 0.f, rsB = 0.f;
#pragma unroll
        for (int f = 0; f < 8; f++) {
            sacc[f][0] = expapx(sacc[f][0] - mnA); rsA += sacc[f][0];
            sacc[f][1] = expapx(sacc[f][1] - mnA); rsA += sacc[f][1];
            sacc[f][2] = expapx(sacc[f][2] - mnB); rsB += sacc[f][2];
            sacc[f][3] = expapx(sacc[f][3] - mnB); rsB += sacc[f][3];
        }
        rsA += __shfl_xor_sync(0xffffffffu, rsA, 1);
        rsA += __shfl_xor_sync(0xffffffffu, rsA, 2);
        rsB += __shfl_xor_sync(0xffffffffu, rsB, 1);
        rsB += __shfl_xor_sync(0xffffffffu, rsB, 2);
        lA = lA * aA + rsA; mA = mnA;
        lB = lB * aB + rsB; mB = mnB;
#pragma unroll
        for (int f = 0; f < 8; f++) {
            O[f][0] *= aA; O[f][1] *= aA; O[f][2] *= aB; O[f][3] *= aB;
        }

        // ---- O += P V  (P packed in-register from S fragments) ----
#pragma unroll
        for (int ks = 0; ks < 4; ks++) {
            uint32_t vbh[4][4], vbl[4][4];
#pragma unroll
            for (int t = 0; t < 4; t++) {
                uint32_t off = (uint32_t)((ks * 16 + (((lane >> 3) & 1) << 3) + (lane & 7)) * 144
                             + (t * 16 + ((lane >> 4) << 3)) * 2);
                LDSM4T(vbh[t], sb + 18432 + off);
                LDSM4T(vbl[t], sb + 27648 + off);
            }
            const float* s0 = sacc[2*ks];
            const float* s1 = sacc[2*ks+1];
            uint32_t ph[4], pl[4];
            ph[0] = packbf(s0[0], s0[1]); ph[1] = packbf(s0[2], s0[3]);
            ph[2] = packbf(s1[0], s1[1]); ph[3] = packbf(s1[2], s1[3]);
            pl[0] = packbf(s0[0]-lo16f(ph[0]), s0[1]-hi16f(ph[0]));
            pl[1] = packbf(s0[2]-lo16f(ph[1]), s0[3]-hi16f(ph[1]));
            pl[2] = packbf(s1[0]-lo16f(ph[2]), s1[1]-hi16f(ph[2]));
            pl[3] = packbf(s1[2]-lo16f(ph[3]), s1[3]-hi16f(ph[3]));
#pragma unroll
            for (int f = 0; f < 8; f++) {
                int t = f >> 1, p = (f & 1) << 1;
                MMA_BF16(O[f], ph, vbh[t][p], vbh[t][p+1]);
                MMA_BF16(O[f], ph, vbl[t][p], vbl[t][p+1]);
                MMA_BF16(O[f], pl, vbh[t][p], vbh[t][p+1]);
            }
        }
        __syncthreads();   // all warps done with K/V smem before next tile load
    }

    // ---- epilogue: O/l, write preout splits into g_xhi/g_xlo ----
    float iA = __fdividef(1.f, lA), iB = __fdividef(1.f, lB);
    int rA = q0 + warp * 16 + (lane >> 2);
#pragma unroll
    for (int f = 0; f < 8; f++) {
        int colhd = f * 8 + ((lane & 3) << 1);
        size_t ia = ((size_t)b * SEQ + rA) * DMODEL + h * HDIM + colhd;
        size_t ib = ia + (size_t)8 * DMODEL;
        float x0 = O[f][0] * iA, x1 = O[f][1] * iA;
        float x2 = O[f][2] * iB, x3 = O[f][3] * iB;
        uint32_t hA = packbf(x0, x1);
        uint32_t lAw = packbf(x0 - lo16f(hA), x1 - hi16f(hA));
        uint32_t hB = packbf(x2, x3);
        uint32_t lBw = packbf(x2 - lo16f(hB), x3 - hi16f(hB));
        *(uint32_t*)&g_xhi[ia] = hA; *(uint32_t*)&g_xlo[ia] = lAw;
        *(uint32_t*)&g_xhi[ib] = hB; *(uint32_t*)&g_xlo[ib] = lBw;
    }
}

// =================================================================
extern "C" void kernel_launch(void* const* d_in, const int* in_sizes, int n_in,
                              void* d_out, int out_size)
{
    (void)in_sizes; (void)n_in; (void)out_size;
    const float* x  = (const float*)d_in[0];
    const float* Wq = (const float*)d_in[1];
    const float* bq = (const float*)d_in[2];
    const float* Wk = (const float*)d_in[3];
    const float* bk = (const float*)d_in[4];
    const float* Wv = (const float*)d_in[5];
    const float* bv = (const float*)d_in[6];
    const float* Wo = (const float*)d_in[7];
    const float* bo = (const float*)d_in[8];
    float* out = (float*)d_out;

    void *pqh,*pql,*pkh,*pkl,*pvh,*pvl,*pxh,*pxl,*pwh,*pwl;
    cudaGetSymbolAddress(&pqh, g_qhi); cudaGetSymbolAddress(&pql, g_qlo);
    cudaGetSymbolAddress(&pkh, g_khi); cudaGetSymbolAddress(&pkl, g_klo);
    cudaGetSymbolAddress(&pvh, g_vhi); cudaGetSymbolAddress(&pvl, g_vlo);
    cudaGetSymbolAddress(&pxh, g_xhi); cudaGetSymbolAddress(&pxl, g_xlo);
    cudaGetSymbolAddress(&pwh, g_whi); cudaGetSymbolAddress(&pwl, g_wlo);

    __nv_bfloat16* xhi = (__nv_bfloat16*)pxh;
    __nv_bfloat16* xlo = (__nv_bfloat16*)pxl;
    __nv_bfloat16* whi = (__nv_bfloat16*)pwh;
    __nv_bfloat16* wlo = (__nv_bfloat16*)pwl;
    const size_t WSZ = (size_t)DMODEL * DMODEL;

    cudaFuncSetAttribute(mma_gemm_kernel,
                         cudaFuncAttributeMaxDynamicSharedMemorySize, GEMM_SMEM);

    // ---- split conversions ----
    const int XN4 = NTOK * DMODEL / 4;
    const int WN4 = (int)(WSZ / 4);
    split_kernel<<<XN4 / 256, 256>>>(x,  xhi, xlo, XN4);
    split_kernel<<<WN4 / 256, 256>>>(Wq, whi + 0*WSZ, wlo + 0*WSZ, WN4);
    split_kernel<<<WN4 / 256, 256>>>(Wk, whi + 1*WSZ, wlo + 1*WSZ, WN4);
    split_kernel<<<WN4 / 256, 256>>>(Wv, whi + 2*WSZ, wlo + 2*WSZ, WN4);
    split_kernel<<<WN4 / 256, 256>>>(Wo, whi + 3*WSZ, wlo + 3*WSZ, WN4);

    // ---- QKV projections (write bf16 hi/lo, head-major; Q pre-scaled) ----
    dim3 gg(NTOK / 128, DMODEL / 64);      // 64 x 12
    mma_gemm_kernel<<<gg, 256, GEMM_SMEM>>>(xhi, xlo, whi + 0*WSZ, wlo + 0*WSZ, bq,
        nullptr, (__nv_bfloat16*)pqh, (__nv_bfloat16*)pql, 1, 0.125f);
    mma_gemm_kernel<<<gg, 256, GEMM_SMEM>>>(xhi, xlo, whi + 1*WSZ, wlo + 1*WSZ, bk,
        nullptr, (__nv_bfloat16*)pkh, (__nv_bfloat16*)pkl, 1, 1.0f);
    mma_gemm_kernel<<<gg, 256, GEMM_SMEM>>>(xhi, xlo, whi + 2*WSZ, wlo + 2*WSZ, bv,
        nullptr, (__nv_bfloat16*)pvh, (__nv_bfloat16*)pvl, 1, 1.0f);

    // ---- tensor-core flash attention (writes preout splits to xhi/xlo) ----
    dim3 gf(SEQ / 128, NHEAD, BATCH);      // 32 x 12 x 2
    flash_tc_kernel<<<gf, 256>>>();

    // ---- output projection ----
    mma_gemm_kernel<<<gg, 256, GEMM_SMEM>>>(xhi, xlo, whi + 3*WSZ, wlo + 3*WSZ, bo,
        out, nullptr, nullptr, 0, 1.0f);
}

// round 9
// speedup vs baseline: 2.6317x; 1.0994x over previous
#include <cuda_runtime.h>
#include <cuda_bf16.h>
#include <math.h>
#include <stdint.h>

#define BATCH 2
#define SEQ   4096
#define DMODEL 768
#define NHEAD 12
#define HDIM  64
#define NTOK  (BATCH*SEQ)   // 8192

// ---------------- scratch (no allocations allowed) ----------------
__device__ __nv_bfloat16 g_qhi[(size_t)BATCH*NHEAD*SEQ*HDIM];  // [B,H,S,64], pre-scaled 1/8
__device__ __nv_bfloat16 g_qlo[(size_t)BATCH*NHEAD*SEQ*HDIM];
__device__ __nv_bfloat16 g_khi[(size_t)BATCH*NHEAD*SEQ*HDIM];
__device__ __nv_bfloat16 g_klo[(size_t)BATCH*NHEAD*SEQ*HDIM];
__device__ __nv_bfloat16 g_vhi[(size_t)BATCH*NHEAD*SEQ*HDIM];
__device__ __nv_bfloat16 g_vlo[(size_t)BATCH*NHEAD*SEQ*HDIM];

__device__ __nv_bfloat16 g_xhi[(size_t)NTOK*DMODEL];   // x splits; later reused for preout splits
__device__ __nv_bfloat16 g_xlo[(size_t)NTOK*DMODEL];
__device__ __nv_bfloat16 g_whi[4*(size_t)DMODEL*DMODEL];
__device__ __nv_bfloat16 g_wlo[4*(size_t)DMODEL*DMODEL];

// ================= portable (sm_80+) asm helpers =================
__device__ __forceinline__ uint32_t smem_u32(const void* p){
    uint32_t a;
    asm("{ .reg .u64 t; cvta.to.shared.u64 t, %1; cvt.u32.u64 %0, t; }" : "=r"(a) : "l"(p));
    return a;
}

#define CP_ASYNC16(dst, src) \
    asm volatile("cp.async.cg.shared.global [%0], [%1], 16;" :: "r"(dst), "l"(src))
#define CP_COMMIT()  asm volatile("cp.async.commit_group;" ::: "memory")
#define CP_WAIT0()   asm volatile("cp.async.wait_group 0;" ::: "memory")
#define CP_WAIT1()   asm volatile("cp.async.wait_group 1;" ::: "memory")

#define LDSM4(r, addr) \
    asm volatile("ldmatrix.sync.aligned.m8n8.x4.shared.b16 {%0,%1,%2,%3}, [%4];" \
        : "=r"((r)[0]), "=r"((r)[1]), "=r"((r)[2]), "=r"((r)[3]) : "r"(addr))

#define LDSM4T(r, addr) \
    asm volatile("ldmatrix.sync.aligned.m8n8.x4.trans.shared.b16 {%0,%1,%2,%3}, [%4];" \
        : "=r"((r)[0]), "=r"((r)[1]), "=r"((r)[2]), "=r"((r)[3]) : "r"(addr))

#define MMA_BF16(d, a, b0, b1) \
    asm volatile("mma.sync.aligned.m16n8k16.row.col.f32.bf16.bf16.f32 " \
        "{%0,%1,%2,%3}, {%4,%5,%6,%7}, {%8,%9}, {%0,%1,%2,%3};" \
        : "+f"((d)[0]), "+f"((d)[1]), "+f"((d)[2]), "+f"((d)[3]) \
        : "r"((a)[0]), "r"((a)[1]), "r"((a)[2]), "r"((a)[3]), "r"(b0), "r"(b1))

// pack two f32 into bf16x2: lo half = first arg, hi half = second
__device__ __forceinline__ uint32_t packbf(float lo, float hi){
    uint32_t r;
    asm("cvt.rn.bf16x2.f32 %0, %1, %2;" : "=r"(r) : "f"(hi), "f"(lo));
    return r;
}
__device__ __forceinline__ float lo16f(uint32_t p){ return __uint_as_float(p << 16); }
__device__ __forceinline__ float hi16f(uint32_t p){ return __uint_as_float(p & 0xffff0000u); }

// fast exp on fma/alu pipes (avoids MUFU throughput wall).
__device__ __forceinline__ float expapx(float t){
    t = fmaxf(t, -80.f);
    float z = t * 1.4426950408889634f;
    float n = rintf(z);
    float u = fmaf(n, -0.69314718056f, t);
    float p = 0.008333333f;
    p = fmaf(p, u, 0.041666667f);
    p = fmaf(p, u, 0.166666667f);
    p = fmaf(p, u, 0.5f);
    p = fmaf(p, u, 1.0f);
    p = fmaf(p, u, 1.0f);
    int ei = ((int)n + 127) << 23;
    return p * __int_as_float(ei);
}

// =================================================================
// split kernel
// =================================================================
__global__ void split_kernel(const float* __restrict__ in,
                             __nv_bfloat16* __restrict__ hi,
                             __nv_bfloat16* __restrict__ lo, int n4)
{
    int i = blockIdx.x * blockDim.x + threadIdx.x;
    if (i >= n4) return;
    float4 v = ((const float4*)in)[i];
    uint32_t h0 = packbf(v.x, v.y);
    uint32_t h1 = packbf(v.z, v.w);
    uint32_t l0 = packbf(v.x - lo16f(h0), v.y - hi16f(h0));
    uint32_t l1 = packbf(v.z - lo16f(h1), v.w - hi16f(h1));
    ((uint32_t*)hi)[2*i]   = h0;
    ((uint32_t*)hi)[2*i+1] = h1;
    ((uint32_t*)lo)[2*i]   = l0;
    ((uint32_t*)lo)[2*i+1] = l1;
}

// =================================================================
// mma.sync split-bf16 GEMM, 2-stage double-buffered smem pipeline.
// =================================================================
#define GKC 64
#define NKCH (DMODEL/GKC)          // 12
#define APITCH_B 144

#define SG_AHI 0
#define SG_ALO 18432
#define SG_BHI 36864
#define SG_BLO 46080
#define GEMM_STAGE 55296
#define GEMM_SMEM  (2*GEMM_STAGE)  // 110592

__global__ __launch_bounds__(256, 2) void mma_gemm_kernel(
    const __nv_bfloat16* __restrict__ Xhi, const __nv_bfloat16* __restrict__ Xlo,
    const __nv_bfloat16* __restrict__ Whi, const __nv_bfloat16* __restrict__ Wlo,
    const float* __restrict__ bias, float* __restrict__ outF,
    __nv_bfloat16* __restrict__ outHi, __nv_bfloat16* __restrict__ outLo,
    int mode, float scale)
{
    extern __shared__ char smem[];
    const uint32_t sb = smem_u32(smem);
    const int tid  = threadIdx.x;
    const int wid  = tid >> 5, lane = tid & 31;
    const int wm   = wid >> 1;
    const int wn   = wid & 1;
    const int row0 = blockIdx.x * 128;
    const int col0 = blockIdx.y * 64;

    float acc[2][4][4] = {};

    auto load_ab = [&](int k0, uint32_t st){
#pragma unroll
        for (int it = 0; it < 4; it++) {
            int g = it * 256 + tid;
            int r = g >> 3, c = g & 7;
            uint32_t soff = (uint32_t)(r * APITCH_B + c * 16);
            size_t goff = (size_t)(row0 + r) * DMODEL + k0 + c * 8;
            CP_ASYNC16(st + SG_AHI + soff, Xhi + goff);
            CP_ASYNC16(st + SG_ALO + soff, Xlo + goff);
        }
#pragma unroll
        for (int it = 0; it < 2; it++) {
            int g = it * 256 + tid;
            int r = g >> 3, c = g & 7;
            uint32_t soff = (uint32_t)(r * APITCH_B + c * 16);
            size_t goff = (size_t)(col0 + r) * DMODEL + k0 + c * 8;
            CP_ASYNC16(st + SG_BHI + soff, Whi + goff);
            CP_ASYNC16(st + SG_BLO + soff, Wlo + goff);
        }
        CP_COMMIT();
    };

    load_ab(0, sb);                       // prologue

    for (int ck = 0; ck < NKCH; ck++) {
        if (ck + 1 < NKCH) {
            load_ab((ck + 1) * GKC, sb + (uint32_t)((ck + 1) & 1) * GEMM_STAGE);
            CP_WAIT1();                   // stage ck resident, ck+1 in flight
        } else {
            CP_WAIT0();
        }
        __syncthreads();

        const uint32_t st = sb + (uint32_t)(ck & 1) * GEMM_STAGE;
#pragma unroll
        for (int s = 0; s < 4; s++) {
            const int kk = s * 16;
            uint32_t ah[2][4], al[2][4], bh[2][4], bl[2][4];
#pragma unroll
            for (int mf = 0; mf < 2; mf++) {
                int arow = wm * 32 + mf * 16 + (lane & 15);
                uint32_t off = (uint32_t)(arow * APITCH_B + (kk + ((lane >> 4) << 3)) * 2);
                LDSM4(ah[mf], st + SG_AHI + off);
                LDSM4(al[mf], st + SG_ALO + off);
            }
#pragma unroll
            for (int q = 0; q < 2; q++) {
                int brow = wn * 32 + q * 16 + ((lane >> 4) << 3) + (lane & 7);
                uint32_t off = (uint32_t)(brow * APITCH_B + (kk + (((lane >> 3) & 1) << 3)) * 2);
                LDSM4(bh[q], st + SG_BHI + off);
                LDSM4(bl[q], st + SG_BLO + off);
            }
#pragma unroll
            for (int mf = 0; mf < 2; mf++)
#pragma unroll
                for (int nf = 0; nf < 4; nf++) {
                    int q = nf >> 1, p = (nf & 1) << 1;
                    MMA_BF16(acc[mf][nf], ah[mf], bh[q][p], bh[q][p+1]);
                    MMA_BF16(acc[mf][nf], ah[mf], bl[q][p], bl[q][p+1]);
                    MMA_BF16(acc[mf][nf], al[mf], bh[q][p], bh[q][p+1]);
                }
        }
        __syncthreads();                  // done reading stage ck before overwrite
    }

    // ---- epilogue ----
#pragma unroll
    for (int mf = 0; mf < 2; mf++)
#pragma unroll
        for (int nf = 0; nf < 4; nf++) {
            int colh = wn * 32 + nf * 8 + ((lane & 3) << 1);
            int col  = col0 + colh;
            float2 bb = *(const float2*)&bias[col];
#pragma unroll
            for (int hr = 0; hr < 2; hr++) {
                int n = row0 + wm * 32 + mf * 16 + (lane >> 2) + hr * 8;
                float vx = acc[mf][nf][hr*2+0] + bb.x;
                float vy = acc[mf][nf][hr*2+1] + bb.y;
                if (mode) {
                    vx *= scale; vy *= scale;
                    int b = n >> 12, sq = n & (SEQ - 1);
                    size_t idx = (((size_t)(b * NHEAD + blockIdx.y)) * SEQ + sq) * HDIM + colh;
                    uint32_t hp = packbf(vx, vy);
                    uint32_t lp = packbf(vx - lo16f(hp), vy - hi16f(hp));
                    *(uint32_t*)&outHi[idx] = hp;
                    *(uint32_t*)&outLo[idx] = lp;
                } else {
                    float2 v; v.x = vx; v.y = vy;
                    *(float2*)&outF[(size_t)n * DMODEL + col] = v;
                }
            }
        }
}

// =================================================================
// Tensor-core flash attention, causal. BQ=128, BK=64, 8 warps.
// 2-stage double-buffered K/V smem pipeline.
// stage layout: Khi +0, Klo +9216, Vhi +18432, Vlo +27648 (pitch 144)
// =================================================================
#define FL_STAGE 36864
#define FL_SMEM  (2*FL_STAGE)    // 73728

__global__ __launch_bounds__(256) void flash_tc_kernel()
{
    extern __shared__ char smemf[];
    const uint32_t sb = smem_u32(smemf);
    const int tid = threadIdx.x;
    const int warp = tid >> 5, lane = tid & 31;
    const int qt = blockIdx.x, h = blockIdx.y, b = blockIdx.z;
    const size_t bh = (size_t)(b * NHEAD + h) * SEQ;
    const int q0 = qt * 128;

    // ---- stage Q tile into stage0 (hi at +0, lo at +18432), extract frags ----
#pragma unroll
    for (int it = 0; it < 4; it++) {
        int g = it * 256 + tid;
        int r = g >> 3, c = g & 7;
        size_t src = (bh + q0 + r) * 64 + c * 8;
        uint32_t dst = sb + r * 144 + c * 16;
        CP_ASYNC16(dst,         g_qhi + src);
        CP_ASYNC16(dst + 18432, g_qlo + src);
    }
    CP_COMMIT(); CP_WAIT0(); __syncthreads();

    uint32_t qh[4][4], ql[4][4];
    {
        int qr = warp * 16 + (lane & 15);
#pragma unroll
        for (int s = 0; s < 4; s++) {
            uint32_t off = (uint32_t)(qr * 144 + (s * 16 + ((lane >> 4) << 3)) * 2);
            LDSM4(qh[s], sb + off);
            LDSM4(ql[s], sb + 18432 + off);
        }
    }
    __syncthreads();   // Q consumed; stage0 reusable

    auto load_kv = [&](int key0, uint32_t st){
#pragma unroll
        for (int it = 0; it < 2; it++) {
            int g = it * 256 + tid;
            int r = g >> 3, c = g & 7;
            size_t src = (bh + key0 + r) * 64 + c * 8;
            uint32_t dst = st + r * 144 + c * 16;
            CP_ASYNC16(dst,         g_khi + src);
            CP_ASYNC16(dst +  9216, g_klo + src);
            CP_ASYNC16(dst + 18432, g_vhi + src);
            CP_ASYNC16(dst + 27648, g_vlo + src);
        }
        CP_COMMIT();
    };

    float O[8][4] = {};
    float mA = -1e30f, mB = -1e30f, lA = 0.f, lB = 0.f;

    const int nkt = 2 * qt + 2;
    load_kv(0, sb);                       // prologue

    for (int kt = 0; kt < nkt; kt++) {
        if (kt + 1 < nkt) {
            load_kv((kt + 1) * 64, sb + (uint32_t)((kt + 1) & 1) * FL_STAGE);
            CP_WAIT1();
        } else {
            CP_WAIT0();
        }
        __syncthreads();

        const uint32_t st = sb + (uint32_t)(kt & 1) * FL_STAGE;
        const int key0 = kt * 64;

        // ---- S = (Q/8) K^T ----
        float sacc[8][4] = {};
#pragma unroll
        for (int s = 0; s < 4; s++) {
            uint32_t kbh[4][4], kbl[4][4];
#pragma unroll
            for (int t = 0; t < 4; t++) {
                uint32_t off = (uint32_t)((t * 16 + ((lane >> 4) << 3) + (lane & 7)) * 144
                             + (s * 16 + (((lane >> 3) & 1) << 3)) * 2);
                LDSM4(kbh[t], st + off);
                LDSM4(kbl[t], st + 9216 + off);
            }
#pragma unroll
            for (int f = 0; f < 8; f++) {
                int t = f >> 1, p = (f & 1) << 1;
                MMA_BF16(sacc[f], qh[s], kbh[t][p], kbh[t][p+1]);
                MMA_BF16(sacc[f], qh[s], kbl[t][p], kbl[t][p+1]);
                MMA_BF16(sacc[f], ql[s], kbh[t][p], kbh[t][p+1]);
            }
        }

        // ---- causal mask (only diagonal tiles) ----
        if (kt >= 2 * qt) {
            int rA = q0 + warp * 16 + (lane >> 2);
#pragma unroll
            for (int f = 0; f < 8; f++) {
                int cb = key0 + f * 8 + ((lane & 3) << 1);
                if (cb     > rA    ) sacc[f][0] = -1e30f;
                if (cb + 1 > rA    ) sacc[f][1] = -1e30f;
                if (cb     > rA + 8) sacc[f][2] = -1e30f;
                if (cb + 1 > rA + 8) sacc[f][3] = -1e30f;
            }
        }

        // ---- online softmax (rows live in quads: xor 1,2) ----
        float mtA = -1e30f, mtB = -1e30f;
#pragma unroll
        for (int f = 0; f < 8; f++) {
            mtA = fmaxf(mtA, fmaxf(sacc[f][0], sacc[f][1]));
            mtB = fmaxf(mtB, fmaxf(sacc[f][2], sacc[f][3]));
        }
        mtA = fmaxf(mtA, __shfl_xor_sync(0xffffffffu, mtA, 1));
        mtA = fmaxf(mtA, __shfl_xor_sync(0xffffffffu, mtA, 2));
        mtB = fmaxf(mtB, __shfl_xor_sync(0xffffffffu, mtB, 1));
        mtB = fmaxf(mtB, __shfl_xor_sync(0xffffffffu, mtB, 2));
        float mnA = fmaxf(mA, mtA), mnB = fmaxf(mB, mtB);
        float aA = expapx(mA - mnA), aB = expapx(mB - mnB);
        float rsA = 0.f, rsB = 0.f;
#pragma unroll
        for (int f = 0; f < 8; f++) {
            sacc[f][0] = expapx(sacc[f][0] - mnA); rsA += sacc[f][0];
            sacc[f][1] = expapx(sacc[f][1] - mnA); rsA += sacc[f][1];
            sacc[f][2] = expapx(sacc[f][2] - mnB); rsB += sacc[f][2];
            sacc[f][3] = expapx(sacc[f][3] - mnB); rsB += sacc[f][3];
        }
        rsA += __shfl_xor_sync(0xffffffffu, rsA, 1);
        rsA += __shfl_xor_sync(0xffffffffu, rsA, 2);
        rsB += __shfl_xor_sync(0xffffffffu, rsB, 1);
        rsB += __shfl_xor_sync(0xffffffffu, rsB, 2);
        lA = lA * aA + rsA; mA = mnA;
        lB = lB * aB + rsB; mB = mnB;
#pragma unroll
        for (int f = 0; f < 8; f++) {
            O[f][0] *= aA; O[f][1] *= aA; O[f][2] *= aB; O[f][3] *= aB;
        }

        // ---- O += P V  (P packed in-register from S fragments) ----
#pragma unroll
        for (int ks = 0; ks < 4; ks++) {
            uint32_t vbh[4][4], vbl[4][4];
#pragma unroll
            for (int t = 0; t < 4; t++) {
                uint32_t off = (uint32_t)((ks * 16 + (((lane >> 3) & 1) << 3) + (lane & 7)) * 144
                             + (t * 16 + ((lane >> 4) << 3)) * 2);
                LDSM4T(vbh[t], st + 18432 + off);
                LDSM4T(vbl[t], st + 27648 + off);
            }
            const float* s0 = sacc[2*ks];
            const float* s1 = sacc[2*ks+1];
            uint32_t ph[4], pl[4];
            ph[0] = packbf(s0[0], s0[1]); ph[1] = packbf(s0[2], s0[3]);
            ph[2] = packbf(s1[0], s1[1]); ph[3] = packbf(s1[2], s1[3]);
            pl[0] = packbf(s0[0]-lo16f(ph[0]), s0[1]-hi16f(ph[0]));
            pl[1] = packbf(s0[2]-lo16f(ph[1]), s0[3]-hi16f(ph[1]));
            pl[2] = packbf(s1[0]-lo16f(ph[2]), s1[1]-hi16f(ph[2]));
            pl[3] = packbf(s1[2]-lo16f(ph[3]), s1[3]-hi16f(ph[3]));
#pragma unroll
            for (int f = 0; f < 8; f++) {
                int t = f >> 1, p = (f & 1) << 1;
                MMA_BF16(O[f], ph, vbh[t][p], vbh[t][p+1]);
                MMA_BF16(O[f], ph, vbl[t][p], vbl[t][p+1]);
                MMA_BF16(O[f], pl, vbh[t][p], vbh[t][p+1]);
            }
        }
        __syncthreads();   // done reading stage kt before it is refilled
    }

    // ---- epilogue: O/l, write preout splits into g_xhi/g_xlo ----
    float iA = __fdividef(1.f, lA), iB = __fdividef(1.f, lB);
    int rA = q0 + warp * 16 + (lane >> 2);
#pragma unroll
    for (int f = 0; f < 8; f++) {
        int colhd = f * 8 + ((lane & 3) << 1);
        size_t ia = ((size_t)b * SEQ + rA) * DMODEL + h * HDIM + colhd;
        size_t ib = ia + (size_t)8 * DMODEL;
        float x0 = O[f][0] * iA, x1 = O[f][1] * iA;
        float x2 = O[f][2] * iB, x3 = O[f][3] * iB;
        uint32_t hA = packbf(x0, x1);
        uint32_t lAw = packbf(x0 - lo16f(hA), x1 - hi16f(hA));
        uint32_t hB = packbf(x2, x3);
        uint32_t lBw = packbf(x2 - lo16f(hB), x3 - hi16f(hB));
        *(uint32_t*)&g_xhi[ia] = hA; *(uint32_t*)&g_xlo[ia] = lAw;
        *(uint32_t*)&g_xhi[ib] = hB; *(uint32_t*)&g_xlo[ib] = lBw;
    }
}

// =================================================================
extern "C" void kernel_launch(void* const* d_in, const int* in_sizes, int n_in,
                              void* d_out, int out_size)
{
    (void)in_sizes; (void)n_in; (void)out_size;
    const float* x  = (const float*)d_in[0];
    const float* Wq = (const float*)d_in[1];
    const float* bq = (const float*)d_in[2];
    const float* Wk = (const float*)d_in[3];
    const float* bk = (const float*)d_in[4];
    const float* Wv = (const float*)d_in[5];
    const float* bv = (const float*)d_in[6];
    const float* Wo = (const float*)d_in[7];
    const float* bo = (const float*)d_in[8];
    float* out = (float*)d_out;

    void *pqh,*pql,*pkh,*pkl,*pvh,*pvl,*pxh,*pxl,*pwh,*pwl;
    cudaGetSymbolAddress(&pqh, g_qhi); cudaGetSymbolAddress(&pql, g_qlo);
    cudaGetSymbolAddress(&pkh, g_khi); cudaGetSymbolAddress(&pkl, g_klo);
    cudaGetSymbolAddress(&pvh, g_vhi); cudaGetSymbolAddress(&pvl, g_vlo);
    cudaGetSymbolAddress(&pxh, g_xhi); cudaGetSymbolAddress(&pxl, g_xlo);
    cudaGetSymbolAddress(&pwh, g_whi); cudaGetSymbolAddress(&pwl, g_wlo);

    __nv_bfloat16* xhi = (__nv_bfloat16*)pxh;
    __nv_bfloat16* xlo = (__nv_bfloat16*)pxl;
    __nv_bfloat16* whi = (__nv_bfloat16*)pwh;
    __nv_bfloat16* wlo = (__nv_bfloat16*)pwl;
    const size_t WSZ = (size_t)DMODEL * DMODEL;

    cudaFuncSetAttribute(mma_gemm_kernel,
                         cudaFuncAttributeMaxDynamicSharedMemorySize, GEMM_SMEM);
    cudaFuncSetAttribute(flash_tc_kernel,
                         cudaFuncAttributeMaxDynamicSharedMemorySize, FL_SMEM);

    // ---- split conversions ----
    const int XN4 = NTOK * DMODEL / 4;
    const int WN4 = (int)(WSZ / 4);
    split_kernel<<<XN4 / 256, 256>>>(x,  xhi, xlo, XN4);
    split_kernel<<<WN4 / 256, 256>>>(Wq, whi + 0*WSZ, wlo + 0*WSZ, WN4);
    split_kernel<<<WN4 / 256, 256>>>(Wk, whi + 1*WSZ, wlo + 1*WSZ, WN4);
    split_kernel<<<WN4 / 256, 256>>>(Wv, whi + 2*WSZ, wlo + 2*WSZ, WN4);
    split_kernel<<<WN4 / 256, 256>>>(Wo, whi + 3*WSZ, wlo + 3*WSZ, WN4);

    // ---- QKV projections (write bf16 hi/lo, head-major; Q pre-scaled) ----
    dim3 gg(NTOK / 128, DMODEL / 64);      // 64 x 12
    mma_gemm_kernel<<<gg, 256, GEMM_SMEM>>>(xhi, xlo, whi + 0*WSZ, wlo + 0*WSZ, bq,
        nullptr, (__nv_bfloat16*)pqh, (__nv_bfloat16*)pql, 1, 0.125f);
    mma_gemm_kernel<<<gg, 256, GEMM_SMEM>>>(xhi, xlo, whi + 1*WSZ, wlo + 1*WSZ, bk,
        nullptr, (__nv_bfloat16*)pkh, (__nv_bfloat16*)pkl, 1, 1.0f);
    mma_gemm_kernel<<<gg, 256, GEMM_SMEM>>>(xhi, xlo, whi + 2*WSZ, wlo + 2*WSZ, bv,
        nullptr, (__nv_bfloat16*)pvh, (__nv_bfloat16*)pvl, 1, 1.0f);

    // ---- tensor-core flash attention (writes preout splits to xhi/xlo) ----
    dim3 gf(SEQ / 128, NHEAD, BATCH);      // 32 x 12 x 2
    flash_tc_kernel<<<gf, 256, FL_SMEM>>>();

    // ---- output projection ----
    mma_gemm_kernel<<<gg, 256, GEMM_SMEM>>>(xhi, xlo, whi + 3*WSZ, wlo + 3*WSZ, bo,
        out, nullptr, nullptr, 0, 1.0f);
}

// round 10
// speedup vs baseline: 2.9265x; 1.1120x over previous
#include <cuda_runtime.h>
#include <cuda_bf16.h>
#include <math.h>
#include <stdint.h>

#define BATCH 2
#define SEQ   4096
#define DMODEL 768
#define NHEAD 12
#define HDIM  64
#define NTOK  (BATCH*SEQ)   // 8192

// ---------------- scratch (no allocations allowed) ----------------
__device__ __nv_bfloat16 g_qhi[(size_t)BATCH*NHEAD*SEQ*HDIM];  // [B,H,S,64], pre-scaled 1/8
__device__ __nv_bfloat16 g_qlo[(size_t)BATCH*NHEAD*SEQ*HDIM];
__device__ __nv_bfloat16 g_khi[(size_t)BATCH*NHEAD*SEQ*HDIM];
__device__ __nv_bfloat16 g_klo[(size_t)BATCH*NHEAD*SEQ*HDIM];
__device__ __nv_bfloat16 g_vhi[(size_t)BATCH*NHEAD*SEQ*HDIM];
__device__ __nv_bfloat16 g_vlo[(size_t)BATCH*NHEAD*SEQ*HDIM];

__device__ __nv_bfloat16 g_xhi[(size_t)NTOK*DMODEL];   // x splits; later reused for preout splits
__device__ __nv_bfloat16 g_xlo[(size_t)NTOK*DMODEL];
__device__ __nv_bfloat16 g_whi[4*(size_t)DMODEL*DMODEL];
__device__ __nv_bfloat16 g_wlo[4*(size_t)DMODEL*DMODEL];

// ================= portable (sm_80+) asm helpers =================
__device__ __forceinline__ uint32_t smem_u32(const void* p){
    uint32_t a;
    asm("{ .reg .u64 t; cvta.to.shared.u64 t, %1; cvt.u32.u64 %0, t; }" : "=r"(a) : "l"(p));
    return a;
}

#define CP_ASYNC16(dst, src) \
    asm volatile("cp.async.cg.shared.global [%0], [%1], 16;" :: "r"(dst), "l"(src))
#define CP_COMMIT()  asm volatile("cp.async.commit_group;" ::: "memory")
#define CP_WAIT0()   asm volatile("cp.async.wait_group 0;" ::: "memory")
#define CP_WAIT1()   asm volatile("cp.async.wait_group 1;" ::: "memory")

#define LDSM4(r, addr) \
    asm volatile("ldmatrix.sync.aligned.m8n8.x4.shared.b16 {%0,%1,%2,%3}, [%4];" \
        : "=r"((r)[0]), "=r"((r)[1]), "=r"((r)[2]), "=r"((r)[3]) : "r"(addr))

#define LDSM4T(r, addr) \
    asm volatile("ldmatrix.sync.aligned.m8n8.x4.trans.shared.b16 {%0,%1,%2,%3}, [%4];" \
        : "=r"((r)[0]), "=r"((r)[1]), "=r"((r)[2]), "=r"((r)[3]) : "r"(addr))

#define MMA_BF16(d, a, b0, b1) \
    asm volatile("mma.sync.aligned.m16n8k16.row.col.f32.bf16.bf16.f32 " \
        "{%0,%1,%2,%3}, {%4,%5,%6,%7}, {%8,%9}, {%0,%1,%2,%3};" \
        : "+f"((d)[0]), "+f"((d)[1]), "+f"((d)[2]), "+f"((d)[3]) \
        : "r"((a)[0]), "r"((a)[1]), "r"((a)[2]), "r"((a)[3]), "r"(b0), "r"(b1))

__device__ __forceinline__ uint32_t packbf(float lo, float hi){
    uint32_t r;
    asm("cvt.rn.bf16x2.f32 %0, %1, %2;" : "=r"(r) : "f"(hi), "f"(lo));
    return r;
}
__device__ __forceinline__ float lo16f(uint32_t p){ return __uint_as_float(p << 16); }
__device__ __forceinline__ float hi16f(uint32_t p){ return __uint_as_float(p & 0xffff0000u); }

// fast exp on fma/alu pipes (avoids MUFU throughput wall).
__device__ __forceinline__ float expapx(float t){
    t = fmaxf(t, -80.f);
    float z = t * 1.4426950408889634f;
    float n = rintf(z);
    float u = fmaf(n, -0.69314718056f, t);
    float p = 0.008333333f;
    p = fmaf(p, u, 0.041666667f);
    p = fmaf(p, u, 0.166666667f);
    p = fmaf(p, u, 0.5f);
    p = fmaf(p, u, 1.0f);
    p = fmaf(p, u, 1.0f);
    int ei = ((int)n + 127) << 23;
    return p * __int_as_float(ei);
}

// =================================================================
// split kernel
// =================================================================
__global__ void split_kernel(const float* __restrict__ in,
                             __nv_bfloat16* __restrict__ hi,
                             __nv_bfloat16* __restrict__ lo, int n4)
{
    int i = blockIdx.x * blockDim.x + threadIdx.x;
    if (i >= n4) return;
    float4 v = ((const float4*)in)[i];
    uint32_t h0 = packbf(v.x, v.y);
    uint32_t h1 = packbf(v.z, v.w);
    uint32_t l0 = packbf(v.x - lo16f(h0), v.y - hi16f(h0));
    uint32_t l1 = packbf(v.z - lo16f(h1), v.w - hi16f(h1));
    ((uint32_t*)hi)[2*i]   = h0;
    ((uint32_t*)hi)[2*i+1] = h1;
    ((uint32_t*)lo)[2*i]   = l0;
    ((uint32_t*)lo)[2*i+1] = l1;
}

// =================================================================
// GEMM core machinery (shared by QKV-fused and out-proj kernels)
// CTA tile 128x64, 8 warps (4m x 2n), K-chunks of 64, 2-stage pipe.
// =================================================================
#define GKC 64
#define NKCH (DMODEL/GKC)          // 12
#define APITCH_B 144

#define SG_AHI 0
#define SG_ALO 18432
#define SG_BHI 36864
#define SG_BLO 46080
#define GEMM_STAGE 55296
#define GEMM_SMEM  (2*GEMM_STAGE)  // 110592

struct GemmAcc { float a[2][4][4]; };

__device__ __forceinline__ void gemm_load_stage(
    uint32_t st, int tid, int row0, int col0, int k0,
    const __nv_bfloat16* Xhi, const __nv_bfloat16* Xlo,
    const __nv_bfloat16* Whi, const __nv_bfloat16* Wlo)
{
#pragma unroll
    for (int it = 0; it < 4; it++) {
        int g = it * 256 + tid;
        int r = g >> 3, c = g & 7;
        uint32_t soff = (uint32_t)(r * APITCH_B + c * 16);
        size_t goff = (size_t)(row0 + r) * DMODEL + k0 + c * 8;
        CP_ASYNC16(st + SG_AHI + soff, Xhi + goff);
        CP_ASYNC16(st + SG_ALO + soff, Xlo + goff);
    }
#pragma unroll
    for (int it = 0; it < 2; it++) {
        int g = it * 256 + tid;
        int r = g >> 3, c = g & 7;
        uint32_t soff = (uint32_t)(r * APITCH_B + c * 16);
        size_t goff = (size_t)(col0 + r) * DMODEL + k0 + c * 8;
        CP_ASYNC16(st + SG_BHI + soff, Whi + goff);
        CP_ASYNC16(st + SG_BLO + soff, Wlo + goff);
    }
    CP_COMMIT();
}

__device__ __forceinline__ void gemm_main(
    GemmAcc& A, uint32_t sb, int tid, int row0, int col0,
    const __nv_bfloat16* Xhi, const __nv_bfloat16* Xlo,
    const __nv_bfloat16* Whi, const __nv_bfloat16* Wlo)
{
    const int wid = tid >> 5, lane = tid & 31;
    const int wm = wid >> 1, wn = wid & 1;

    gemm_load_stage(sb, tid, row0, col0, 0, Xhi, Xlo, Whi, Wlo);

    for (int ck = 0; ck < NKCH; ck++) {
        if (ck + 1 < NKCH) {
            gemm_load_stage(sb + (uint32_t)((ck + 1) & 1) * GEMM_STAGE,
                            tid, row0, col0, (ck + 1) * GKC, Xhi, Xlo, Whi, Wlo);
            CP_WAIT1();
        } else {
            CP_WAIT0();
        }
        __syncthreads();

        const uint32_t st = sb + (uint32_t)(ck & 1) * GEMM_STAGE;
#pragma unroll
        for (int s = 0; s < 4; s++) {
            const int kk = s * 16;
            uint32_t ah[2][4], al[2][4], bh[2][4], bl[2][4];
#pragma unroll
            for (int mf = 0; mf < 2; mf++) {
                int arow = wm * 32 + mf * 16 + (lane & 15);
                uint32_t off = (uint32_t)(arow * APITCH_B + (kk + ((lane >> 4) << 3)) * 2);
                LDSM4(ah[mf], st + SG_AHI + off);
                LDSM4(al[mf], st + SG_ALO + off);
            }
#pragma unroll
            for (int q = 0; q < 2; q++) {
                int brow = wn * 32 + q * 16 + ((lane >> 4) << 3) + (lane & 7);
                uint32_t off = (uint32_t)(brow * APITCH_B + (kk + (((lane >> 3) & 1) << 3)) * 2);
                LDSM4(bh[q], st + SG_BHI + off);
                LDSM4(bl[q], st + SG_BLO + off);
            }
#pragma unroll
            for (int mf = 0; mf < 2; mf++)
#pragma unroll
                for (int nf = 0; nf < 4; nf++) {
                    int q = nf >> 1, p = (nf & 1) << 1;
                    MMA_BF16(A.a[mf][nf], ah[mf], bh[q][p], bh[q][p+1]);
                    MMA_BF16(A.a[mf][nf], ah[mf], bl[q][p], bl[q][p+1]);
                    MMA_BF16(A.a[mf][nf], al[mf], bh[q][p], bh[q][p+1]);
                }
        }
        __syncthreads();
    }
}

// ---- fused QKV projection: grid (64, 36); y -> (mat, head) ----
__global__ __launch_bounds__(256, 2) void mma_qkv_kernel(
    const float* __restrict__ biasq, const float* __restrict__ biask,
    const float* __restrict__ biasv)
{
    extern __shared__ char smem[];
    const uint32_t sb = smem_u32(smem);
    const int tid = threadIdx.x;
    const int wid = tid >> 5, lane = tid & 31;
    const int wm = wid >> 1, wn = wid & 1;
    const int mat = blockIdx.y / NHEAD;          // 0=Q 1=K 2=V
    const int hh  = blockIdx.y % NHEAD;
    const int row0 = blockIdx.x * 128;
    const int col0 = hh * 64;
    const size_t WSZ = (size_t)DMODEL * DMODEL;

    const __nv_bfloat16* Whi = g_whi + (size_t)mat * WSZ;
    const __nv_bfloat16* Wlo = g_wlo + (size_t)mat * WSZ;
    const float* bias = (mat == 0) ? biasq : (mat == 1) ? biask : biasv;
    __nv_bfloat16* outHi = (mat == 0) ? g_qhi : (mat == 1) ? g_khi : g_vhi;
    __nv_bfloat16* outLo = (mat == 0) ? g_qlo : (mat == 1) ? g_klo : g_vlo;
    const float scale = (mat == 0) ? 0.125f : 1.0f;

    GemmAcc A = {};
    gemm_main(A, sb, tid, row0, col0, g_xhi, g_xlo, Whi, Wlo);

#pragma unroll
    for (int mf = 0; mf < 2; mf++)
#pragma unroll
        for (int nf = 0; nf < 4; nf++) {
            int colh = wn * 32 + nf * 8 + ((lane & 3) << 1);
            float2 bb = *(const float2*)&bias[col0 + colh];
#pragma unroll
            for (int hr = 0; hr < 2; hr++) {
                int n = row0 + wm * 32 + mf * 16 + (lane >> 2) + hr * 8;
                float vx = (A.a[mf][nf][hr*2+0] + bb.x) * scale;
                float vy = (A.a[mf][nf][hr*2+1] + bb.y) * scale;
                int b = n >> 12, sq = n & (SEQ - 1);
                size_t idx = (((size_t)(b * NHEAD + hh)) * SEQ + sq) * HDIM + colh;
                uint32_t hp = packbf(vx, vy);
                uint32_t lp = packbf(vx - lo16f(hp), vy - hi16f(hp));
                *(uint32_t*)&outHi[idx] = hp;
                *(uint32_t*)&outLo[idx] = lp;
            }
        }
}

// ---- output projection: preout splits (g_xhi/g_xlo) @ Wo^T + bo -> f32 ----
__global__ __launch_bounds__(256, 2) void mma_oproj_kernel(
    const float* __restrict__ bias, float* __restrict__ outF)
{
    extern __shared__ char smem[];
    const uint32_t sb = smem_u32(smem);
    const int tid = threadIdx.x;
    const int wid = tid >> 5, lane = tid & 31;
    const int wm = wid >> 1, wn = wid & 1;
    const int row0 = blockIdx.x * 128;
    const int col0 = blockIdx.y * 64;
    const size_t WSZ = (size_t)DMODEL * DMODEL;

    GemmAcc A = {};
    gemm_main(A, sb, tid, row0, col0, g_xhi, g_xlo, g_whi + 3*WSZ, g_wlo + 3*WSZ);

#pragma unroll
    for (int mf = 0; mf < 2; mf++)
#pragma unroll
        for (int nf = 0; nf < 4; nf++) {
            int colh = wn * 32 + nf * 8 + ((lane & 3) << 1);
            int col  = col0 + colh;
            float2 bb = *(const float2*)&bias[col];
#pragma unroll
            for (int hr = 0; hr < 2; hr++) {
                int n = row0 + wm * 32 + mf * 16 + (lane >> 2) + hr * 8;
                float2 v;
                v.x = A.a[mf][nf][hr*2+0] + bb.x;
                v.y = A.a[mf][nf][hr*2+1] + bb.y;
                *(float2*)&outF[(size_t)n * DMODEL + col] = v;
            }
        }
}

// =================================================================
// Tensor-core flash attention, causal. BQ=128, BK=128, 8 warps.
// 2-stage double-buffered K/V pipeline; P uses hi-only x (Vhi,Vlo).
// stage layout (pitch 144): Khi +0, Klo +18432, Vhi +36864, Vlo +55296
// =================================================================
#define FL_STAGE 73728
#define FL_SMEM  (2*FL_STAGE)    // 147456

__global__ __launch_bounds__(256) void flash_tc_kernel()
{
    extern __shared__ char smemf[];
    const uint32_t sb = smem_u32(smemf);
    const int tid = threadIdx.x;
    const int warp = tid >> 5, lane = tid & 31;
    const int qt = blockIdx.x, h = blockIdx.y, b = blockIdx.z;
    const size_t bh = (size_t)(b * NHEAD + h) * SEQ;
    const int q0 = qt * 128;

    // ---- stage Q tile into stage0 (hi at +0, lo at +18432), extract frags ----
#pragma unroll
    for (int it = 0; it < 4; it++) {
        int g = it * 256 + tid;
        int r = g >> 3, c = g & 7;
        size_t src = (bh + q0 + r) * 64 + c * 8;
        uint32_t dst = sb + r * 144 + c * 16;
        CP_ASYNC16(dst,         g_qhi + src);
        CP_ASYNC16(dst + 18432, g_qlo + src);
    }
    CP_COMMIT(); CP_WAIT0(); __syncthreads();

    uint32_t qh[4][4], ql[4][4];
    {
        int qr = warp * 16 + (lane & 15);
#pragma unroll
        for (int s = 0; s < 4; s++) {
            uint32_t off = (uint32_t)(qr * 144 + (s * 16 + ((lane >> 4) << 3)) * 2);
            LDSM4(qh[s], sb + off);
            LDSM4(ql[s], sb + 18432 + off);
        }
    }
    __syncthreads();   // Q consumed; stage0 reusable

    auto load_kv = [&](int key0, uint32_t st){
#pragma unroll
        for (int it = 0; it < 4; it++) {
            int g = it * 256 + tid;          // 0..1023, 128 rows x 8 granules
            int r = g >> 3, c = g & 7;
            size_t src = (bh + key0 + r) * 64 + c * 8;
            uint32_t dst = st + r * 144 + c * 16;
            CP_ASYNC16(dst,         g_khi + src);
            CP_ASYNC16(dst + 18432, g_klo + src);
            CP_ASYNC16(dst + 36864, g_vhi + src);
            CP_ASYNC16(dst + 55296, g_vlo + src);
        }
        CP_COMMIT();
    };

    float O[8][4] = {};
    float mA = -1e30f, mB = -1e30f, lA = 0.f, lB = 0.f;

    const int nkt = qt + 1;
    load_kv(0, sb);                       // prologue

    for (int kt = 0; kt < nkt; kt++) {
        if (kt + 1 < nkt) {
            load_kv((kt + 1) * 128, sb + (uint32_t)((kt + 1) & 1) * FL_STAGE);
            CP_WAIT1();
        } else {
            CP_WAIT0();
        }
        __syncthreads();

        const uint32_t st = sb + (uint32_t)(kt & 1) * FL_STAGE;
        const int key0 = kt * 128;

        // ---- S = (Q/8) K^T over 128 keys: 16 fragments ----
        float sacc[16][4] = {};
#pragma unroll
        for (int t = 0; t < 8; t++) {      // key 16-groups
            int brow = t * 16 + ((lane >> 4) << 3) + (lane & 7);
#pragma unroll
            for (int s = 0; s < 4; s++) {  // d 16-steps
                uint32_t off = (uint32_t)(brow * 144 + (s * 16 + (((lane >> 3) & 1) << 3)) * 2);
                uint32_t kh[4], kl[4];
                LDSM4(kh, st + off);
                LDSM4(kl, st + 18432 + off);
                MMA_BF16(sacc[2*t],   qh[s], kh[0], kh[1]);
                MMA_BF16(sacc[2*t],   qh[s], kl[0], kl[1]);
                MMA_BF16(sacc[2*t],   ql[s], kh[0], kh[1]);
                MMA_BF16(sacc[2*t+1], qh[s], kh[2], kh[3]);
                MMA_BF16(sacc[2*t+1], qh[s], kl[2], kl[3]);
                MMA_BF16(sacc[2*t+1], ql[s], kh[2], kh[3]);
            }
        }

        // ---- causal mask (diagonal tile only) ----
        if (kt == qt) {
            int rA = q0 + warp * 16 + (lane >> 2);
#pragma unroll
            for (int f = 0; f < 16; f++) {
                int cb = key0 + f * 8 + ((lane & 3) << 1);
                if (cb     > rA    ) sacc[f][0] = -1e30f;
                if (cb + 1 > rA    ) sacc[f][1] = -1e30f;
                if (cb     > rA + 8) sacc[f][2] = -1e30f;
                if (cb + 1 > rA + 8) sacc[f][3] = -1e30f;
            }
        }

        // ---- online softmax (rows in quads: xor 1,2) ----
        float mtA = -1e30f, mtB = -1e30f;
#pragma unroll
        for (int f = 0; f < 16; f++) {
            mtA = fmaxf(mtA, fmaxf(sacc[f][0], sacc[f][1]));
            mtB = fmaxf(mtB, fmaxf(sacc[f][2], sacc[f][3]));
        }
        mtA = fmaxf(mtA, __shfl_xor_sync(0xffffffffu, mtA, 1));
        mtA = fmaxf(mtA, __shfl_xor_sync(0xffffffffu, mtA, 2));
        mtB = fmaxf(mtB, __shfl_xor_sync(0xffffffffu, mtB, 1));
        mtB = fmaxf(mtB, __shfl_xor_sync(0xffffffffu, mtB, 2));
        float mnA = fmaxf(mA, mtA), mnB = fmaxf(mB, mtB);
        float aA = expapx(mA - mnA), aB = expapx(mB - mnB);
        float rsA = 0.f, rsB = 0.f;
#pragma unroll
        for (int f = 0; f < 16; f++) {
            sacc[f][0] = expapx(sacc[f][0] - mnA); rsA += sacc[f][0];
            sacc[f][1] = expapx(sacc[f][1] - mnA); rsA += sacc[f][1];
            sacc[f][2] = expapx(sacc[f][2] - mnB); rsB += sacc[f][2];
            sacc[f][3] = expapx(sacc[f][3] - mnB); rsB += sacc[f][3];
        }
        rsA += __shfl_xor_sync(0xffffffffu, rsA, 1);
        rsA += __shfl_xor_sync(0xffffffffu, rsA, 2);
        rsB += __shfl_xor_sync(0xffffffffu, rsB, 1);
        rsB += __shfl_xor_sync(0xffffffffu, rsB, 2);
        lA = lA * aA + rsA; mA = mnA;
        lB = lB * aB + rsB; mB = mnB;
#pragma unroll
        for (int f = 0; f < 8; f++) {
            O[f][0] *= aA; O[f][1] *= aA; O[f][2] *= aB; O[f][3] *= aB;
        }

        // ---- O += P V  (P hi-only; V hi+lo) ----
#pragma unroll
        for (int ks = 0; ks < 8; ks++) {
            uint32_t vbh[4][4], vbl[4][4];
            int vrow = ks * 16 + (((lane >> 3) & 1) << 3) + (lane & 7);
#pragma unroll
            for (int t = 0; t < 4; t++) {
                uint32_t off = (uint32_t)(vrow * 144 + (t * 16 + ((lane >> 4) << 3)) * 2);
                LDSM4T(vbh[t], st + 36864 + off);
                LDSM4T(vbl[t], st + 55296 + off);
            }
            const float* s0 = sacc[2*ks];
            const float* s1 = sacc[2*ks+1];
            uint32_t ph[4];
            ph[0] = packbf(s0[0], s0[1]); ph[1] = packbf(s0[2], s0[3]);
            ph[2] = packbf(s1[0], s1[1]); ph[3] = packbf(s1[2], s1[3]);
#pragma unroll
            for (int f = 0; f < 8; f++) {
                int t = f >> 1, p = (f & 1) << 1;
                MMA_BF16(O[f], ph, vbh[t][p], vbh[t][p+1]);
                MMA_BF16(O[f], ph, vbl[t][p], vbl[t][p+1]);
            }
        }
        __syncthreads();   // done reading stage kt before it is refilled
    }

    // ---- epilogue: O/l, write preout splits into g_xhi/g_xlo ----
    float iA = __fdividef(1.f, lA), iB = __fdividef(1.f, lB);
    int rA = q0 + warp * 16 + (lane >> 2);
#pragma unroll
    for (int f = 0; f < 8; f++) {
        int colhd = f * 8 + ((lane & 3) << 1);
        size_t ia = ((size_t)b * SEQ + rA) * DMODEL + h * HDIM + colhd;
        size_t ib = ia + (size_t)8 * DMODEL;
        float x0 = O[f][0] * iA, x1 = O[f][1] * iA;
        float x2 = O[f][2] * iB, x3 = O[f][3] * iB;
        uint32_t hA = packbf(x0, x1);
        uint32_t lAw = packbf(x0 - lo16f(hA), x1 - hi16f(hA));
        uint32_t hB = packbf(x2, x3);
        uint32_t lBw = packbf(x2 - lo16f(hB), x3 - hi16f(hB));
        *(uint32_t*)&g_xhi[ia] = hA; *(uint32_t*)&g_xlo[ia] = lAw;
        *(uint32_t*)&g_xhi[ib] = hB; *(uint32_t*)&g_xlo[ib] = lBw;
    }
}

// =================================================================
extern "C" void kernel_launch(void* const* d_in, const int* in_sizes, int n_in,
                              void* d_out, int out_size)
{
    (void)in_sizes; (void)n_in; (void)out_size;
    const float* x  = (const float*)d_in[0];
    const float* Wq = (const float*)d_in[1];
    const float* bq = (const float*)d_in[2];
    const float* Wk = (const float*)d_in[3];
    const float* bk = (const float*)d_in[4];
    const float* Wv = (const float*)d_in[5];
    const float* bv = (const float*)d_in[6];
    const float* Wo = (const float*)d_in[7];
    const float* bo = (const float*)d_in[8];
    float* out = (float*)d_out;

    void *pxh, *pxl, *pwh, *pwl;
    cudaGetSymbolAddress(&pxh, g_xhi); cudaGetSymbolAddress(&pxl, g_xlo);
    cudaGetSymbolAddress(&pwh, g_whi); cudaGetSymbolAddress(&pwl, g_wlo);

    __nv_bfloat16* xhi = (__nv_bfloat16*)pxh;
    __nv_bfloat16* xlo = (__nv_bfloat16*)pxl;
    __nv_bfloat16* whi = (__nv_bfloat16*)pwh;
    __nv_bfloat16* wlo = (__nv_bfloat16*)pwl;
    const size_t WSZ = (size_t)DMODEL * DMODEL;

    cudaFuncSetAttribute(mma_qkv_kernel,
                         cudaFuncAttributeMaxDynamicSharedMemorySize, GEMM_SMEM);
    cudaFuncSetAttribute(mma_oproj_kernel,
                         cudaFuncAttributeMaxDynamicSharedMemorySize, GEMM_SMEM);
    cudaFuncSetAttribute(flash_tc_kernel,
                         cudaFuncAttributeMaxDynamicSharedMemorySize, FL_SMEM);

    // ---- split conversions ----
    const int XN4 = NTOK * DMODEL / 4;
    const int WN4 = (int)(WSZ / 4);
    split_kernel<<<XN4 / 256, 256>>>(x,  xhi, xlo, XN4);
    split_kernel<<<WN4 / 256, 256>>>(Wq, whi + 0*WSZ, wlo + 0*WSZ, WN4);
    split_kernel<<<WN4 / 256, 256>>>(Wk, whi + 1*WSZ, wlo + 1*WSZ, WN4);
    split_kernel<<<WN4 / 256, 256>>>(Wv, whi + 2*WSZ, wlo + 2*WSZ, WN4);
    split_kernel<<<WN4 / 256, 256>>>(Wo, whi + 3*WSZ, wlo + 3*WSZ, WN4);

    // ---- fused QKV projection ----
    dim3 gq(NTOK / 128, 3 * NHEAD);        // 64 x 36
    mma_qkv_kernel<<<gq, 256, GEMM_SMEM>>>(bq, bk, bv);

    // ---- tensor-core flash attention (writes preout splits to xhi/xlo) ----
    dim3 gf(SEQ / 128, NHEAD, BATCH);      // 32 x 12 x 2
    flash_tc_kernel<<<gf, 256, FL_SMEM>>>();

    // ---- output projection ----
    dim3 go(NTOK / 128, DMODEL / 64);      // 64 x 12
    mma_oproj_kernel<<<go, 256, GEMM_SMEM>>>(bo, out);
}

// round 11
// speedup vs baseline: 3.1334x; 1.0707x over previous
#include <cuda_runtime.h>
#include <cuda_bf16.h>
#include <math.h>
#include <stdint.h>

#define BATCH 2
#define SEQ   4096
#define DMODEL 768
#define NHEAD 12
#define HDIM  64
#define NTOK  (BATCH*SEQ)   // 8192

// ---------------- scratch (no allocations allowed) ----------------
__device__ __nv_bfloat16 g_qhi[(size_t)BATCH*NHEAD*SEQ*HDIM];  // [B,H,S,64], pre-scaled 1/8
__device__ __nv_bfloat16 g_qlo[(size_t)BATCH*NHEAD*SEQ*HDIM];
__device__ __nv_bfloat16 g_khi[(size_t)BATCH*NHEAD*SEQ*HDIM];
__device__ __nv_bfloat16 g_klo[(size_t)BATCH*NHEAD*SEQ*HDIM];
__device__ __nv_bfloat16 g_vhi[(size_t)BATCH*NHEAD*SEQ*HDIM];
__device__ __nv_bfloat16 g_vlo[(size_t)BATCH*NHEAD*SEQ*HDIM];

__device__ __nv_bfloat16 g_xhi[(size_t)NTOK*DMODEL];   // x splits; later reused for preout splits
__device__ __nv_bfloat16 g_xlo[(size_t)NTOK*DMODEL];
__device__ __nv_bfloat16 g_whi[4*(size_t)DMODEL*DMODEL];
__device__ __nv_bfloat16 g_wlo[4*(size_t)DMODEL*DMODEL];

// ================= portable (sm_80+) asm helpers =================
__device__ __forceinline__ uint32_t smem_u32(const void* p){
    uint32_t a;
    asm("{ .reg .u64 t; cvta.to.shared.u64 t, %1; cvt.u32.u64 %0, t; }" : "=r"(a) : "l"(p));
    return a;
}

#define CP_ASYNC16(dst, src) \
    asm volatile("cp.async.cg.shared.global [%0], [%1], 16;" :: "r"(dst), "l"(src))
#define CP_COMMIT()  asm volatile("cp.async.commit_group;" ::: "memory")
#define CP_WAIT0()   asm volatile("cp.async.wait_group 0;" ::: "memory")
#define CP_WAIT1()   asm volatile("cp.async.wait_group 1;" ::: "memory")

#define LDSM4(r, addr) \
    asm volatile("ldmatrix.sync.aligned.m8n8.x4.shared.b16 {%0,%1,%2,%3}, [%4];" \
        : "=r"((r)[0]), "=r"((r)[1]), "=r"((r)[2]), "=r"((r)[3]) : "r"(addr))

#define LDSM4T(r, addr) \
    asm volatile("ldmatrix.sync.aligned.m8n8.x4.trans.shared.b16 {%0,%1,%2,%3}, [%4];" \
        : "=r"((r)[0]), "=r"((r)[1]), "=r"((r)[2]), "=r"((r)[3]) : "r"(addr))

#define MMA_BF16(d, a, b0, b1) \
    asm volatile("mma.sync.aligned.m16n8k16.row.col.f32.bf16.bf16.f32 " \
        "{%0,%1,%2,%3}, {%4,%5,%6,%7}, {%8,%9}, {%0,%1,%2,%3};" \
        : "+f"((d)[0]), "+f"((d)[1]), "+f"((d)[2]), "+f"((d)[3]) \
        : "r"((a)[0]), "r"((a)[1]), "r"((a)[2]), "r"((a)[3]), "r"(b0), "r"(b1))

__device__ __forceinline__ uint32_t packbf(float lo, float hi){
    uint32_t r;
    asm("cvt.rn.bf16x2.f32 %0, %1, %2;" : "=r"(r) : "f"(hi), "f"(lo));
    return r;
}
__device__ __forceinline__ float lo16f(uint32_t p){ return __uint_as_float(p << 16); }
__device__ __forceinline__ float hi16f(uint32_t p){ return __uint_as_float(p & 0xffff0000u); }

// =================================================================
// split kernels
// =================================================================
__global__ void split_kernel(const float* __restrict__ in,
                             __nv_bfloat16* __restrict__ hi,
                             __nv_bfloat16* __restrict__ lo, int n4)
{
    int i = blockIdx.x * blockDim.x + threadIdx.x;
    if (i >= n4) return;
    float4 v = ((const float4*)in)[i];
    uint32_t h0 = packbf(v.x, v.y);
    uint32_t h1 = packbf(v.z, v.w);
    uint32_t l0 = packbf(v.x - lo16f(h0), v.y - hi16f(h0));
    uint32_t l1 = packbf(v.z - lo16f(h1), v.w - hi16f(h1));
    ((uint32_t*)hi)[2*i]   = h0;
    ((uint32_t*)hi)[2*i+1] = h1;
    ((uint32_t*)lo)[2*i]   = l0;
    ((uint32_t*)lo)[2*i+1] = l1;
}

// fused 4-weight split: blockIdx.y selects matrix; outputs at mat*WSZ
__global__ void split_w4_kernel(const float* __restrict__ w0, const float* __restrict__ w1,
                                const float* __restrict__ w2, const float* __restrict__ w3,
                                int n4)
{
    int i = blockIdx.x * blockDim.x + threadIdx.x;
    if (i >= n4) return;
    int mat = blockIdx.y;
    const float* in = (mat == 0) ? w0 : (mat == 1) ? w1 : (mat == 2) ? w2 : w3;
    const size_t WSZ = (size_t)DMODEL * DMODEL;
    __nv_bfloat16* hi = g_whi + (size_t)mat * WSZ;
    __nv_bfloat16* lo = g_wlo + (size_t)mat * WSZ;
    float4 v = ((const float4*)in)[i];
    uint32_t h0 = packbf(v.x, v.y);
    uint32_t h1 = packbf(v.z, v.w);
    uint32_t l0 = packbf(v.x - lo16f(h0), v.y - hi16f(h0));
    uint32_t l1 = packbf(v.z - lo16f(h1), v.w - hi16f(h1));
    ((uint32_t*)hi)[2*i]   = h0;
    ((uint32_t*)hi)[2*i+1] = h1;
    ((uint32_t*)lo)[2*i]   = l0;
    ((uint32_t*)lo)[2*i+1] = l1;
}

// =================================================================
// GEMM core machinery (shared by QKV-fused and out-proj kernels)
// CTA tile 128x64, 8 warps (4m x 2n), K-chunks of 64, 2-stage pipe.
// =================================================================
#define GKC 64
#define NKCH (DMODEL/GKC)          // 12
#define APITCH_B 144

#define SG_AHI 0
#define SG_ALO 18432
#define SG_BHI 36864
#define SG_BLO 46080
#define GEMM_STAGE 55296
#define GEMM_SMEM  (2*GEMM_STAGE)  // 110592

struct GemmAcc { float a[2][4][4]; };

__device__ __forceinline__ void gemm_load_stage(
    uint32_t st, int tid, int row0, int col0, int k0,
    const __nv_bfloat16* Xhi, const __nv_bfloat16* Xlo,
    const __nv_bfloat16* Whi, const __nv_bfloat16* Wlo)
{
#pragma unroll
    for (int it = 0; it < 4; it++) {
        int g = it * 256 + tid;
        int r = g >> 3, c = g & 7;
        uint32_t soff = (uint32_t)(r * APITCH_B + c * 16);
        size_t goff = (size_t)(row0 + r) * DMODEL + k0 + c * 8;
        CP_ASYNC16(st + SG_AHI + soff, Xhi + goff);
        CP_ASYNC16(st + SG_ALO + soff, Xlo + goff);
    }
#pragma unroll
    for (int it = 0; it < 2; it++) {
        int g = it * 256 + tid;
        int r = g >> 3, c = g & 7;
        uint32_t soff = (uint32_t)(r * APITCH_B + c * 16);
        size_t goff = (size_t)(col0 + r) * DMODEL + k0 + c * 8;
        CP_ASYNC16(st + SG_BHI + soff, Whi + goff);
        CP_ASYNC16(st + SG_BLO + soff, Wlo + goff);
    }
    CP_COMMIT();
}

__device__ __forceinline__ void gemm_main(
    GemmAcc& A, uint32_t sb, int tid, int row0, int col0,
    const __nv_bfloat16* Xhi, const __nv_bfloat16* Xlo,
    const __nv_bfloat16* Whi, const __nv_bfloat16* Wlo)
{
    const int wid = tid >> 5, lane = tid & 31;
    const int wm = wid >> 1, wn = wid & 1;

    gemm_load_stage(sb, tid, row0, col0, 0, Xhi, Xlo, Whi, Wlo);

    for (int ck = 0; ck < NKCH; ck++) {
        if (ck + 1 < NKCH) {
            gemm_load_stage(sb + (uint32_t)((ck + 1) & 1) * GEMM_STAGE,
                            tid, row0, col0, (ck + 1) * GKC, Xhi, Xlo, Whi, Wlo);
            CP_WAIT1();
        } else {
            CP_WAIT0();
        }
        __syncthreads();

        const uint32_t st = sb + (uint32_t)(ck & 1) * GEMM_STAGE;
#pragma unroll
        for (int s = 0; s < 4; s++) {
            const int kk = s * 16;
            uint32_t ah[2][4], al[2][4], bh[2][4], bl[2][4];
#pragma unroll
            for (int mf = 0; mf < 2; mf++) {
                int arow = wm * 32 + mf * 16 + (lane & 15);
                uint32_t off = (uint32_t)(arow * APITCH_B + (kk + ((lane >> 4) << 3)) * 2);
                LDSM4(ah[mf], st + SG_AHI + off);
                LDSM4(al[mf], st + SG_ALO + off);
            }
#pragma unroll
            for (int q = 0; q < 2; q++) {
                int brow = wn * 32 + q * 16 + ((lane >> 4) << 3) + (lane & 7);
                uint32_t off = (uint32_t)(brow * APITCH_B + (kk + (((lane >> 3) & 1) << 3)) * 2);
                LDSM4(bh[q], st + SG_BHI + off);
                LDSM4(bl[q], st + SG_BLO + off);
            }
#pragma unroll
            for (int mf = 0; mf < 2; mf++)
#pragma unroll
                for (int nf = 0; nf < 4; nf++) {
                    int q = nf >> 1, p = (nf & 1) << 1;
                    MMA_BF16(A.a[mf][nf], ah[mf], bh[q][p], bh[q][p+1]);
                    MMA_BF16(A.a[mf][nf], ah[mf], bl[q][p], bl[q][p+1]);
                    MMA_BF16(A.a[mf][nf], al[mf], bh[q][p], bh[q][p+1]);
                }
        }
        __syncthreads();
    }
}

// ---- fused QKV projection: grid (64, 36); y -> (mat, head) ----
__global__ __launch_bounds__(256, 2) void mma_qkv_kernel(
    const float* __restrict__ biasq, const float* __restrict__ biask,
    const float* __restrict__ biasv)
{
    extern __shared__ char smem[];
    const uint32_t sb = smem_u32(smem);
    const int tid = threadIdx.x;
    const int wid = tid >> 5, lane = tid & 31;
    const int wm = wid >> 1, wn = wid & 1;
    const int mat = blockIdx.y / NHEAD;          // 0=Q 1=K 2=V
    const int hh  = blockIdx.y % NHEAD;
    const int row0 = blockIdx.x * 128;
    const int col0 = hh * 64;
    const size_t WSZ = (size_t)DMODEL * DMODEL;

    const __nv_bfloat16* Whi = g_whi + (size_t)mat * WSZ;
    const __nv_bfloat16* Wlo = g_wlo + (size_t)mat * WSZ;
    const float* bias = (mat == 0) ? biasq : (mat == 1) ? biask : biasv;
    __nv_bfloat16* outHi = (mat == 0) ? g_qhi : (mat == 1) ? g_khi : g_vhi;
    __nv_bfloat16* outLo = (mat == 0) ? g_qlo : (mat == 1) ? g_klo : g_vlo;
    const float scale = (mat == 0) ? 0.125f : 1.0f;

    GemmAcc A = {};
    gemm_main(A, sb, tid, row0, col0, g_xhi, g_xlo, Whi, Wlo);

#pragma unroll
    for (int mf = 0; mf < 2; mf++)
#pragma unroll
        for (int nf = 0; nf < 4; nf++) {
            int colh = wn * 32 + nf * 8 + ((lane & 3) << 1);
            float2 bb = *(const float2*)&bias[col0 + colh];
#pragma unroll
            for (int hr = 0; hr < 2; hr++) {
                int n = row0 + wm * 32 + mf * 16 + (lane >> 2) + hr * 8;
                float vx = (A.a[mf][nf][hr*2+0] + bb.x) * scale;
                float vy = (A.a[mf][nf][hr*2+1] + bb.y) * scale;
                int b = n >> 12, sq = n & (SEQ - 1);
                size_t idx = (((size_t)(b * NHEAD + hh)) * SEQ + sq) * HDIM + colh;
                uint32_t hp = packbf(vx, vy);
                uint32_t lp = packbf(vx - lo16f(hp), vy - hi16f(hp));
                *(uint32_t*)&outHi[idx] = hp;
                *(uint32_t*)&outLo[idx] = lp;
            }
        }
}

// ---- output projection: preout splits (g_xhi/g_xlo) @ Wo^T + bo -> f32 ----
__global__ __launch_bounds__(256, 2) void mma_oproj_kernel(
    const float* __restrict__ bias, float* __restrict__ outF)
{
    extern __shared__ char smem[];
    const uint32_t sb = smem_u32(smem);
    const int tid = threadIdx.x;
    const int wid = tid >> 5, lane = tid & 31;
    const int wm = wid >> 1, wn = wid & 1;
    const int row0 = blockIdx.x * 128;
    const int col0 = blockIdx.y * 64;
    const size_t WSZ = (size_t)DMODEL * DMODEL;

    GemmAcc A = {};
    gemm_main(A, sb, tid, row0, col0, g_xhi, g_xlo, g_whi + 3*WSZ, g_wlo + 3*WSZ);

#pragma unroll
    for (int mf = 0; mf < 2; mf++)
#pragma unroll
        for (int nf = 0; nf < 4; nf++) {
            int colh = wn * 32 + nf * 8 + ((lane & 3) << 1);
            int col  = col0 + colh;
            float2 bb = *(const float2*)&bias[col];
#pragma unroll
            for (int hr = 0; hr < 2; hr++) {
                int n = row0 + wm * 32 + mf * 16 + (lane >> 2) + hr * 8;
                float2 v;
                v.x = A.a[mf][nf][hr*2+0] + bb.x;
                v.y = A.a[mf][nf][hr*2+1] + bb.y;
                *(float2*)&outF[(size_t)n * DMODEL + col] = v;
            }
        }
}

// =================================================================
// Tensor-core flash attention, causal. BQ=128, BK=128, 8 warps.
// 2-stage double-buffered K/V pipeline; full 3-MMA split for S and PV.
// exp via MUFU (__expf) -- fma pipe freed for rescale/pack.
// Longest-first schedule: qt = gridDim.x-1-blockIdx.x.
// stage layout (pitch 144): Khi +0, Klo +18432, Vhi +36864, Vlo +55296
// =================================================================
#define FL_STAGE 73728
#define FL_SMEM  (2*FL_STAGE)    // 147456

__global__ __launch_bounds__(256) void flash_tc_kernel()
{
    extern __shared__ char smemf[];
    const uint32_t sb = smem_u32(smemf);
    const int tid = threadIdx.x;
    const int warp = tid >> 5, lane = tid & 31;
    const int qt = gridDim.x - 1 - blockIdx.x;     // longest CTAs first
    const int h = blockIdx.y, b = blockIdx.z;
    const size_t bh = (size_t)(b * NHEAD + h) * SEQ;
    const int q0 = qt * 128;

    // ---- stage Q tile into stage0 (hi at +0, lo at +18432), extract frags ----
#pragma unroll
    for (int it = 0; it < 4; it++) {
        int g = it * 256 + tid;
        int r = g >> 3, c = g & 7;
        size_t src = (bh + q0 + r) * 64 + c * 8;
        uint32_t dst = sb + r * 144 + c * 16;
        CP_ASYNC16(dst,         g_qhi + src);
        CP_ASYNC16(dst + 18432, g_qlo + src);
    }
    CP_COMMIT(); CP_WAIT0(); __syncthreads();

    uint32_t qh[4][4], ql[4][4];
    {
        int qr = warp * 16 + (lane & 15);
#pragma unroll
        for (int s = 0; s < 4; s++) {
            uint32_t off = (uint32_t)(qr * 144 + (s * 16 + ((lane >> 4) << 3)) * 2);
            LDSM4(qh[s], sb + off);
            LDSM4(ql[s], sb + 18432 + off);
        }
    }
    __syncthreads();   // Q consumed; stage0 reusable

    auto load_kv = [&](int key0, uint32_t st){
#pragma unroll
        for (int it = 0; it < 4; it++) {
            int g = it * 256 + tid;          // 0..1023, 128 rows x 8 granules
            int r = g >> 3, c = g & 7;
            size_t src = (bh + key0 + r) * 64 + c * 8;
            uint32_t dst = st + r * 144 + c * 16;
            CP_ASYNC16(dst,         g_khi + src);
            CP_ASYNC16(dst + 18432, g_klo + src);
            CP_ASYNC16(dst + 36864, g_vhi + src);
            CP_ASYNC16(dst + 55296, g_vlo + src);
        }
        CP_COMMIT();
    };

    float O[8][4] = {};
    float mA = -1e30f, mB = -1e30f, lA = 0.f, lB = 0.f;

    const int nkt = qt + 1;
    load_kv(0, sb);                       // prologue

    for (int kt = 0; kt < nkt; kt++) {
        if (kt + 1 < nkt) {
            load_kv((kt + 1) * 128, sb + (uint32_t)((kt + 1) & 1) * FL_STAGE);
            CP_WAIT1();
        } else {
            CP_WAIT0();
        }
        __syncthreads();

        const uint32_t st = sb + (uint32_t)(kt & 1) * FL_STAGE;
        const int key0 = kt * 128;

        // ---- S = (Q/8) K^T over 128 keys: 16 fragments ----
        float sacc[16][4] = {};
#pragma unroll
        for (int t = 0; t < 8; t++) {      // key 16-groups
            int brow = t * 16 + ((lane >> 4) << 3) + (lane & 7);
#pragma unroll
            for (int s = 0; s < 4; s++) {  // d 16-steps
                uint32_t off = (uint32_t)(brow * 144 + (s * 16 + (((lane >> 3) & 1) << 3)) * 2);
                uint32_t kh[4], kl[4];
                LDSM4(kh, st + off);
                LDSM4(kl, st + 18432 + off);
                MMA_BF16(sacc[2*t],   qh[s], kh[0], kh[1]);
                MMA_BF16(sacc[2*t],   qh[s], kl[0], kl[1]);
                MMA_BF16(sacc[2*t],   ql[s], kh[0], kh[1]);
                MMA_BF16(sacc[2*t+1], qh[s], kh[2], kh[3]);
                MMA_BF16(sacc[2*t+1], qh[s], kl[2], kl[3]);
                MMA_BF16(sacc[2*t+1], ql[s], kh[2], kh[3]);
            }
        }

        // ---- causal mask (diagonal tile only) ----
        if (kt == qt) {
            int rA = q0 + warp * 16 + (lane >> 2);
#pragma unroll
            for (int f = 0; f < 16; f++) {
                int cb = key0 + f * 8 + ((lane & 3) << 1);
                if (cb     > rA    ) sacc[f][0] = -1e30f;
                if (cb + 1 > rA    ) sacc[f][1] = -1e30f;
                if (cb     > rA + 8) sacc[f][2] = -1e30f;
                if (cb + 1 > rA + 8) sacc[f][3] = -1e30f;
            }
        }

        // ---- online softmax (rows in quads: xor 1,2); exp on MUFU ----
        float mtA = -1e30f, mtB = -1e30f;
#pragma unroll
        for (int f = 0; f < 16; f++) {
            mtA = fmaxf(mtA, fmaxf(sacc[f][0], sacc[f][1]));
            mtB = fmaxf(mtB, fmaxf(sacc[f][2], sacc[f][3]));
        }
        mtA = fmaxf(mtA, __shfl_xor_sync(0xffffffffu, mtA, 1));
        mtA = fmaxf(mtA, __shfl_xor_sync(0xffffffffu, mtA, 2));
        mtB = fmaxf(mtB, __shfl_xor_sync(0xffffffffu, mtB, 1));
        mtB = fmaxf(mtB, __shfl_xor_sync(0xffffffffu, mtB, 2));
        float mnA = fmaxf(mA, mtA), mnB = fmaxf(mB, mtB);
        float aA = __expf(mA - mnA), aB = __expf(mB - mnB);
        float rsA = 0.f, rsB = 0.f;
#pragma unroll
        for (int f = 0; f < 16; f++) {
            sacc[f][0] = __expf(sacc[f][0] - mnA); rsA += sacc[f][0];
            sacc[f][1] = __expf(sacc[f][1] - mnA); rsA += sacc[f][1];
            sacc[f][2] = __expf(sacc[f][2] - mnB); rsB += sacc[f][2];
            sacc[f][3] = __expf(sacc[f][3] - mnB); rsB += sacc[f][3];
        }
        rsA += __shfl_xor_sync(0xffffffffu, rsA, 1);
        rsA += __shfl_xor_sync(0xffffffffu, rsA, 2);
        rsB += __shfl_xor_sync(0xffffffffu, rsB, 1);
        rsB += __shfl_xor_sync(0xffffffffu, rsB, 2);
        lA = lA * aA + rsA; mA = mnA;
        lB = lB * aB + rsB; mB = mnB;
#pragma unroll
        for (int f = 0; f < 8; f++) {
            O[f][0] *= aA; O[f][1] *= aA; O[f][2] *= aB; O[f][3] *= aB;
        }

        // ---- O += P V  (P hi+lo; V hi+lo; 3-MMA split) ----
#pragma unroll
        for (int ks = 0; ks < 8; ks++) {
            uint32_t vbh[4][4], vbl[4][4];
            int vrow = ks * 16 + (((lane >> 3) & 1) << 3) + (lane & 7);
#pragma unroll
            for (int t = 0; t < 4; t++) {
                uint32_t off = (uint32_t)(vrow * 144 + (t * 16 + ((lane >> 4) << 3)) * 2);
                LDSM4T(vbh[t], st + 36864 + off);
                LDSM4T(vbl[t], st + 55296 + off);
            }
            const float* s0 = sacc[2*ks];
            const float* s1 = sacc[2*ks+1];
            uint32_t ph[4], pl[4];
            ph[0] = packbf(s0[0], s0[1]); ph[1] = packbf(s0[2], s0[3]);
            ph[2] = packbf(s1[0], s1[1]); ph[3] = packbf(s1[2], s1[3]);
            pl[0] = packbf(s0[0]-lo16f(ph[0]), s0[1]-hi16f(ph[0]));
            pl[1] = packbf(s0[2]-lo16f(ph[1]), s0[3]-hi16f(ph[1]));
            pl[2] = packbf(s1[0]-lo16f(ph[2]), s1[1]-hi16f(ph[2]));
            pl[3] = packbf(s1[2]-lo16f(ph[3]), s1[3]-hi16f(ph[3]));
#pragma unroll
            for (int f = 0; f < 8; f++) {
                int t = f >> 1, p = (f & 1) << 1;
                MMA_BF16(O[f], ph, vbh[t][p], vbh[t][p+1]);
                MMA_BF16(O[f], ph, vbl[t][p], vbl[t][p+1]);
                MMA_BF16(O[f], pl, vbh[t][p], vbh[t][p+1]);
            }
        }
        __syncthreads();   // done reading stage kt before it is refilled
    }

    // ---- epilogue: O/l, write preout splits into g_xhi/g_xlo ----
    float iA = __fdividef(1.f, lA), iB = __fdividef(1.f, lB);
    int rA = q0 + warp * 16 + (lane >> 2);
#pragma unroll
    for (int f = 0; f < 8; f++) {
        int colhd = f * 8 + ((lane & 3) << 1);
        size_t ia = ((size_t)b * SEQ + rA) * DMODEL + h * HDIM + colhd;
        size_t ib = ia + (size_t)8 * DMODEL;
        float x0 = O[f][0] * iA, x1 = O[f][1] * iA;
        float x2 = O[f][2] * iB, x3 = O[f][3] * iB;
        uint32_t hA = packbf(x0, x1);
        uint32_t lAw = packbf(x0 - lo16f(hA), x1 - hi16f(hA));
        uint32_t hB = packbf(x2, x3);
        uint32_t lBw = packbf(x2 - lo16f(hB), x3 - hi16f(hB));
        *(uint32_t*)&g_xhi[ia] = hA; *(uint32_t*)&g_xlo[ia] = lAw;
        *(uint32_t*)&g_xhi[ib] = hB; *(uint32_t*)&g_xlo[ib] = lBw;
    }
}

// =================================================================
extern "C" void kernel_launch(void* const* d_in, const int* in_sizes, int n_in,
                              void* d_out, int out_size)
{
    (void)in_sizes; (void)n_in; (void)out_size;
    const float* x  = (const float*)d_in[0];
    const float* Wq = (const float*)d_in[1];
    const float* bq = (const float*)d_in[2];
    const float* Wk = (const float*)d_in[3];
    const float* bk = (const float*)d_in[4];
    const float* Wv = (const float*)d_in[5];
    const float* bv = (const float*)d_in[6];
    const float* Wo = (const float*)d_in[7];
    const float* bo = (const float*)d_in[8];
    float* out = (float*)d_out;

    void *pxh, *pxl;
    cudaGetSymbolAddress(&pxh, g_xhi); cudaGetSymbolAddress(&pxl, g_xlo);
    __nv_bfloat16* xhi = (__nv_bfloat16*)pxh;
    __nv_bfloat16* xlo = (__nv_bfloat16*)pxl;

    cudaFuncSetAttribute(mma_qkv_kernel,
                         cudaFuncAttributeMaxDynamicSharedMemorySize, GEMM_SMEM);
    cudaFuncSetAttribute(mma_oproj_kernel,
                         cudaFuncAttributeMaxDynamicSharedMemorySize, GEMM_SMEM);
    cudaFuncSetAttribute(flash_tc_kernel,
                         cudaFuncAttributeMaxDynamicSharedMemorySize, FL_SMEM);

    // ---- split conversions ----
    const int XN4 = NTOK * DMODEL / 4;
    const int WN4 = (int)((size_t)DMODEL * DMODEL / 4);
    split_kernel<<<XN4 / 256, 256>>>(x, xhi, xlo, XN4);
    dim3 gw(WN4 / 256, 4);
    split_w4_kernel<<<gw, 256>>>(Wq, Wk, Wv, Wo, WN4);

    // ---- fused QKV projection ----
    dim3 gq(NTOK / 128, 3 * NHEAD);        // 64 x 36
    mma_qkv_kernel<<<gq, 256, GEMM_SMEM>>>(bq, bk, bv);

    // ---- tensor-core flash attention (writes preout splits to xhi/xlo) ----
    dim3 gf(SEQ / 128, NHEAD, BATCH);      // 32 x 12 x 2
    flash_tc_kernel<<<gf, 256, FL_SMEM>>>();

    // ---- output projection ----
    dim3 go(NTOK / 128, DMODEL / 64);      // 64 x 12
    mma_oproj_kernel<<<go, 256, GEMM_SMEM>>>(bo, out);
}

// round 13
// speedup vs baseline: 3.2235x; 1.0288x over previous
#include <cuda_runtime.h>
#include <cuda_bf16.h>
#include <math.h>
#include <stdint.h>

#define BATCH 2
#define SEQ   4096
#define DMODEL 768
#define NHEAD 12
#define HDIM  64
#define NTOK  (BATCH*SEQ)   // 8192

// ---------------- scratch (no allocations allowed) ----------------
__device__ __nv_bfloat16 g_qhi[(size_t)BATCH*NHEAD*SEQ*HDIM];  // [B,H,S,64], pre-scaled 1/8
__device__ __nv_bfloat16 g_qlo[(size_t)BATCH*NHEAD*SEQ*HDIM];
__device__ __nv_bfloat16 g_khi[(size_t)BATCH*NHEAD*SEQ*HDIM];
__device__ __nv_bfloat16 g_klo[(size_t)BATCH*NHEAD*SEQ*HDIM];
__device__ __nv_bfloat16 g_vhi[(size_t)BATCH*NHEAD*SEQ*HDIM];
__device__ __nv_bfloat16 g_vlo[(size_t)BATCH*NHEAD*SEQ*HDIM];

__device__ __nv_bfloat16 g_xhi[(size_t)NTOK*DMODEL];   // x splits; later reused for preout splits
__device__ __nv_bfloat16 g_xlo[(size_t)NTOK*DMODEL];
__device__ __nv_bfloat16 g_whi[4*(size_t)DMODEL*DMODEL];
__device__ __nv_bfloat16 g_wlo[4*(size_t)DMODEL*DMODEL];

// ================= portable (sm_80+) asm helpers =================
__device__ __forceinline__ uint32_t smem_u32(const void* p){
    uint32_t a;
    asm("{ .reg .u64 t; cvta.to.shared.u64 t, %1; cvt.u32.u64 %0, t; }" : "=r"(a) : "l"(p));
    return a;
}

#define CP_ASYNC16(dst, src) \
    asm volatile("cp.async.cg.shared.global [%0], [%1], 16;" :: "r"(dst), "l"(src))
#define CP_COMMIT()  asm volatile("cp.async.commit_group;" ::: "memory")
#define CP_WAIT0()   asm volatile("cp.async.wait_group 0;" ::: "memory")
#define CP_WAIT1()   asm volatile("cp.async.wait_group 1;" ::: "memory")
#define CP_WAIT2()   asm volatile("cp.async.wait_group 2;" ::: "memory")

#define LDSM4(r, addr) \
    asm volatile("ldmatrix.sync.aligned.m8n8.x4.shared.b16 {%0,%1,%2,%3}, [%4];" \
        : "=r"((r)[0]), "=r"((r)[1]), "=r"((r)[2]), "=r"((r)[3]) : "r"(addr))

#define LDSM4T(r, addr) \
    asm volatile("ldmatrix.sync.aligned.m8n8.x4.trans.shared.b16 {%0,%1,%2,%3}, [%4];" \
        : "=r"((r)[0]), "=r"((r)[1]), "=r"((r)[2]), "=r"((r)[3]) : "r"(addr))

#define MMA_BF16(d, a, b0, b1) \
    asm volatile("mma.sync.aligned.m16n8k16.row.col.f32.bf16.bf16.f32 " \
        "{%0,%1,%2,%3}, {%4,%5,%6,%7}, {%8,%9}, {%0,%1,%2,%3};" \
        : "+f"((d)[0]), "+f"((d)[1]), "+f"((d)[2]), "+f"((d)[3]) \
        : "r"((a)[0]), "r"((a)[1]), "r"((a)[2]), "r"((a)[3]), "r"(b0), "r"(b1))

__device__ __forceinline__ uint32_t packbf(float lo, float hi){
    uint32_t r;
    asm("cvt.rn.bf16x2.f32 %0, %1, %2;" : "=r"(r) : "f"(hi), "f"(lo));
    return r;
}
__device__ __forceinline__ float lo16f(uint32_t p){ return __uint_as_float(p << 16); }
__device__ __forceinline__ float hi16f(uint32_t p){ return __uint_as_float(p & 0xffff0000u); }

// =================================================================
// split kernels
// =================================================================
__global__ void split_kernel(const float* __restrict__ in,
                             __nv_bfloat16* __restrict__ hi,
                             __nv_bfloat16* __restrict__ lo, int n4)
{
    int i = blockIdx.x * blockDim.x + threadIdx.x;
    if (i >= n4) return;
    float4 v = ((const float4*)in)[i];
    uint32_t h0 = packbf(v.x, v.y);
    uint32_t h1 = packbf(v.z, v.w);
    uint32_t l0 = packbf(v.x - lo16f(h0), v.y - hi16f(h0));
    uint32_t l1 = packbf(v.z - lo16f(h1), v.w - hi16f(h1));
    ((uint32_t*)hi)[2*i]   = h0;
    ((uint32_t*)hi)[2*i+1] = h1;
    ((uint32_t*)lo)[2*i]   = l0;
    ((uint32_t*)lo)[2*i+1] = l1;
}

// fused 4-weight split: blockIdx.y selects matrix; outputs at mat*WSZ
__global__ void split_w4_kernel(const float* __restrict__ w0, const float* __restrict__ w1,
                                const float* __restrict__ w2, const float* __restrict__ w3,
                                int n4)
{
    int i = blockIdx.x * blockDim.x + threadIdx.x;
    if (i >= n4) return;
    int mat = blockIdx.y;
    const float* in = (mat == 0) ? w0 : (mat == 1) ? w1 : (mat == 2) ? w2 : w3;
    const size_t WSZ = (size_t)DMODEL * DMODEL;
    __nv_bfloat16* hi = g_whi + (size_t)mat * WSZ;
    __nv_bfloat16* lo = g_wlo + (size_t)mat * WSZ;
    float4 v = ((const float4*)in)[i];
    uint32_t h0 = packbf(v.x, v.y);
    uint32_t h1 = packbf(v.z, v.w);
    uint32_t l0 = packbf(v.x - lo16f(h0), v.y - hi16f(h0));
    uint32_t l1 = packbf(v.z - lo16f(h1), v.w - hi16f(h1));
    ((uint32_t*)hi)[2*i]   = h0;
    ((uint32_t*)hi)[2*i+1] = h1;
    ((uint32_t*)lo)[2*i]   = l0;
    ((uint32_t*)lo)[2*i+1] = l1;
}

// =================================================================
// GEMM core machinery (shared by QKV-fused and out-proj kernels)
// CTA tile 128x64, 8 warps (4m x 2n), K-chunks of 64, 2-stage pipe.
// =================================================================
#define GKC 64
#define NKCH (DMODEL/GKC)          // 12
#define APITCH_B 144

#define SG_AHI 0
#define SG_ALO 18432
#define SG_BHI 36864
#define SG_BLO 46080
#define GEMM_STAGE 55296
#define GEMM_SMEM  (2*GEMM_STAGE)  // 110592

struct GemmAcc { float a[2][4][4]; };

__device__ __forceinline__ void gemm_load_stage(
    uint32_t st, int tid, int row0, int col0, int k0,
    const __nv_bfloat16* Xhi, const __nv_bfloat16* Xlo,
    const __nv_bfloat16* Whi, const __nv_bfloat16* Wlo)
{
#pragma unroll
    for (int it = 0; it < 4; it++) {
        int g = it * 256 + tid;
        int r = g >> 3, c = g & 7;
        uint32_t soff = (uint32_t)(r * APITCH_B + c * 16);
        size_t goff = (size_t)(row0 + r) * DMODEL + k0 + c * 8;
        CP_ASYNC16(st + SG_AHI + soff, Xhi + goff);
        CP_ASYNC16(st + SG_ALO + soff, Xlo + goff);
    }
#pragma unroll
    for (int it = 0; it < 2; it++) {
        int g = it * 256 + tid;
        int r = g >> 3, c = g & 7;
        uint32_t soff = (uint32_t)(r * APITCH_B + c * 16);
        size_t goff = (size_t)(col0 + r) * DMODEL + k0 + c * 8;
        CP_ASYNC16(st + SG_BHI + soff, Whi + goff);
        CP_ASYNC16(st + SG_BLO + soff, Wlo + goff);
    }
    CP_COMMIT();
}

__device__ __forceinline__ void gemm_main(
    GemmAcc& A, uint32_t sb, int tid, int row0, int col0,
    const __nv_bfloat16* Xhi, const __nv_bfloat16* Xlo,
    const __nv_bfloat16* Whi, const __nv_bfloat16* Wlo)
{
    const int wid = tid >> 5, lane = tid & 31;
    const int wm = wid >> 1, wn = wid & 1;

    gemm_load_stage(sb, tid, row0, col0, 0, Xhi, Xlo, Whi, Wlo);

    for (int ck = 0; ck < NKCH; ck++) {
        if (ck + 1 < NKCH) {
            gemm_load_stage(sb + (uint32_t)((ck + 1) & 1) * GEMM_STAGE,
                            tid, row0, col0, (ck + 1) * GKC, Xhi, Xlo, Whi, Wlo);
            CP_WAIT1();
        } else {
            CP_WAIT0();
        }
        __syncthreads();

        const uint32_t st = sb + (uint32_t)(ck & 1) * GEMM_STAGE;
#pragma unroll
        for (int s = 0; s < 4; s++) {
            const int kk = s * 16;
            uint32_t ah[2][4], al[2][4], bh[2][4], bl[2][4];
#pragma unroll
            for (int mf = 0; mf < 2; mf++) {
                int arow = wm * 32 + mf * 16 + (lane & 15);
                uint32_t off = (uint32_t)(arow * APITCH_B + (kk + ((lane >> 4) << 3)) * 2);
                LDSM4(ah[mf], st + SG_AHI + off);
                LDSM4(al[mf], st + SG_ALO + off);
            }
#pragma unroll
            for (int q = 0; q < 2; q++) {
                int brow = wn * 32 + q * 16 + ((lane >> 4) << 3) + (lane & 7);
                uint32_t off = (uint32_t)(brow * APITCH_B + (kk + (((lane >> 3) & 1) << 3)) * 2);
                LDSM4(bh[q], st + SG_BHI + off);
                LDSM4(bl[q], st + SG_BLO + off);
            }
#pragma unroll
            for (int mf = 0; mf < 2; mf++)
#pragma unroll
                for (int nf = 0; nf < 4; nf++) {
                    int q = nf >> 1, p = (nf & 1) << 1;
                    MMA_BF16(A.a[mf][nf], ah[mf], bh[q][p], bh[q][p+1]);
                    MMA_BF16(A.a[mf][nf], ah[mf], bl[q][p], bl[q][p+1]);
                    MMA_BF16(A.a[mf][nf], al[mf], bh[q][p], bh[q][p+1]);
                }
        }
        __syncthreads();
    }
}

// ---- fused QKV projection: grid (64, 36); y -> (mat, head) ----
__global__ __launch_bounds__(256, 2) void mma_qkv_kernel(
    const float* __restrict__ biasq, const float* __restrict__ biask,
    const float* __restrict__ biasv)
{
    extern __shared__ char smem[];
    const uint32_t sb = smem_u32(smem);
    const int tid = threadIdx.x;
    const int wid = tid >> 5, lane = tid & 31;
    const int wm = wid >> 1, wn = wid & 1;
    const int mat = blockIdx.y / NHEAD;          // 0=Q 1=K 2=V
    const int hh  = blockIdx.y % NHEAD;
    const int row0 = blockIdx.x * 128;
    const int col0 = hh * 64;
    const size_t WSZ = (size_t)DMODEL * DMODEL;

    const __nv_bfloat16* Whi = g_whi + (size_t)mat * WSZ;
    const __nv_bfloat16* Wlo = g_wlo + (size_t)mat * WSZ;
    const float* bias = (mat == 0) ? biasq : (mat == 1) ? biask : biasv;
    __nv_bfloat16* outHi = (mat == 0) ? g_qhi : (mat == 1) ? g_khi : g_vhi;
    __nv_bfloat16* outLo = (mat == 0) ? g_qlo : (mat == 1) ? g_klo : g_vlo;
    const float scale = (mat == 0) ? 0.125f : 1.0f;

    GemmAcc A = {};
    gemm_main(A, sb, tid, row0, col0, g_xhi, g_xlo, Whi, Wlo);

#pragma unroll
    for (int mf = 0; mf < 2; mf++)
#pragma unroll
        for (int nf = 0; nf < 4; nf++) {
            int colh = wn * 32 + nf * 8 + ((lane & 3) << 1);
            float2 bb = *(const float2*)&bias[col0 + colh];
#pragma unroll
            for (int hr = 0; hr < 2; hr++) {
                int n = row0 + wm * 32 + mf * 16 + (lane >> 2) + hr * 8;
                float vx = (A.a[mf][nf][hr*2+0] + bb.x) * scale;
                float vy = (A.a[mf][nf][hr*2+1] + bb.y) * scale;
                int b = n >> 12, sq = n & (SEQ - 1);
                size_t idx = (((size_t)(b * NHEAD + hh)) * SEQ + sq) * HDIM + colh;
                uint32_t hp = packbf(vx, vy);
                uint32_t lp = packbf(vx - lo16f(hp), vy - hi16f(hp));
                *(uint32_t*)&outHi[idx] = hp;
                *(uint32_t*)&outLo[idx] = lp;
            }
        }
}

// ---- output projection: preout splits (g_xhi/g_xlo) @ Wo^T + bo -> f32 ----
__global__ __launch_bounds__(256, 2) void mma_oproj_kernel(
    const float* __restrict__ bias, float* __restrict__ outF)
{
    extern __shared__ char smem[];
    const uint32_t sb = smem_u32(smem);
    const int tid = threadIdx.x;
    const int wid = tid >> 5, lane = tid & 31;
    const int wm = wid >> 1, wn = wid & 1;
    const int row0 = blockIdx.x * 128;
    const int col0 = blockIdx.y * 64;
    const size_t WSZ = (size_t)DMODEL * DMODEL;

    GemmAcc A = {};
    gemm_main(A, sb, tid, row0, col0, g_xhi, g_xlo, g_whi + 3*WSZ, g_wlo + 3*WSZ);

#pragma unroll
    for (int mf = 0; mf < 2; mf++)
#pragma unroll
        for (int nf = 0; nf < 4; nf++) {
            int colh = wn * 32 + nf * 8 + ((lane & 3) << 1);
            int col  = col0 + colh;
            float2 bb = *(const float2*)&bias[col];
#pragma unroll
            for (int hr = 0; hr < 2; hr++) {
                int n = row0 + wm * 32 + mf * 16 + (lane >> 2) + hr * 8;
                float2 v;
                v.x = A.a[mf][nf][hr*2+0] + bb.x;
                v.y = A.a[mf][nf][hr*2+1] + bb.y;
                *(float2*)&outF[(size_t)n * DMODEL + col] = v;
            }
        }
}

// =================================================================
// Tensor-core flash attention, causal. BQ=128, BK=128, 8 warps.
// 3-stage double-buffered K/V pipeline; full 3-MMA split for S and PV.
// exp is LAZY: computed inside the PV loop so MUFU overlaps tensor MMAs.
// Longest-first schedule: qt = gridDim.x-1-blockIdx.x.
// stage layout (pitch 144): Khi +0, Klo +18432, Vhi +36864, Vlo +55296
// =================================================================
#define FL_STAGE 73728
#define FL_SMEM  (3*FL_STAGE)    // 221184

__global__ __launch_bounds__(256) void flash_tc_kernel()
{
    extern __shared__ char smemf[];
    const uint32_t sb = smem_u32(smemf);
    const int tid = threadIdx.x;
    const int warp = tid >> 5, lane = tid & 31;
    const int qt = gridDim.x - 1 - blockIdx.x;     // longest CTAs first
    const int h = blockIdx.y, b = blockIdx.z;
    const size_t bh = (size_t)(b * NHEAD + h) * SEQ;
    const int q0 = qt * 128;

    // ---- stage Q tile into stage0 (hi at +0, lo at +18432), extract frags ----
#pragma unroll
    for (int it = 0; it < 4; it++) {
        int g = it * 256 + tid;
        int r = g >> 3, c = g & 7;
        size_t src = (bh + q0 + r) * 64 + c * 8;
        uint32_t dst = sb + r * 144 + c * 16;
        CP_ASYNC16(dst,         g_qhi + src);
        CP_ASYNC16(dst + 18432, g_qlo + src);
    }
    CP_COMMIT(); CP_WAIT0(); __syncthreads();

    uint32_t qh[4][4], ql[4][4];
    {
        int qr = warp * 16 + (lane & 15);
#pragma unroll
        for (int s = 0; s < 4; s++) {
            uint32_t off = (uint32_t)(qr * 144 + (s * 16 + ((lane >> 4) << 3)) * 2);
            LDSM4(qh[s], sb + off);
            LDSM4(ql[s], sb + 18432 + off);
        }
    }
    __syncthreads();   // Q consumed; stage0 reusable

    auto load_kv = [&](int key0, uint32_t st){
#pragma unroll
        for (int it = 0; it < 4; it++) {
            int g = it * 256 + tid;          // 0..1023, 128 rows x 8 granules
            int r = g >> 3, c = g & 7;
            size_t src = (bh + key0 + r) * 64 + c * 8;
            uint32_t dst = st + r * 144 + c * 16;
            CP_ASYNC16(dst,         g_khi + src);
            CP_ASYNC16(dst + 18432, g_klo + src);
            CP_ASYNC16(dst + 36864, g_vhi + src);
            CP_ASYNC16(dst + 55296, g_vlo + src);
        }
        CP_COMMIT();
    };

    float O[8][4] = {};
    float mA = -1e30f, mB = -1e30f, lA = 0.f, lB = 0.f;

    const int nkt = qt + 1;
    load_kv(0, sb);                                   // prologue: tile 0
    if (nkt > 1) load_kv(128, sb + FL_STAGE);         // prologue: tile 1

    for (int kt = 0; kt < nkt; kt++) {
        if (kt + 2 < nkt) {
            load_kv((kt + 2) * 128, sb + (uint32_t)((kt + 2) % 3) * FL_STAGE);
            CP_WAIT2();
        } else if (kt + 1 < nkt) {
            CP_WAIT1();
        } else {
            CP_WAIT0();
        }
        __syncthreads();

        const uint32_t st = sb + (uint32_t)(kt % 3) * FL_STAGE;
        const int key0 = kt * 128;

        // ---- S = (Q/8) K^T over 128 keys: 16 fragments ----
        float sacc[16][4] = {};
#pragma unroll
        for (int t = 0; t < 8; t++) {      // key 16-groups
            int brow = t * 16 + ((lane >> 4) << 3) + (lane & 7);
#pragma unroll
            for (int s = 0; s < 4; s++) {  // d 16-steps
                uint32_t off = (uint32_t)(brow * 144 + (s * 16 + (((lane >> 3) & 1) << 3)) * 2);
                uint32_t kh[4], kl[4];
                LDSM4(kh, st + off);
                LDSM4(kl, st + 18432 + off);
                MMA_BF16(sacc[2*t],   qh[s], kh[0], kh[1]);
                MMA_BF16(sacc[2*t],   qh[s], kl[0], kl[1]);
                MMA_BF16(sacc[2*t],   ql[s], kh[0], kh[1]);
                MMA_BF16(sacc[2*t+1], qh[s], kh[2], kh[3]);
                MMA_BF16(sacc[2*t+1], qh[s], kl[2], kl[3]);
                MMA_BF16(sacc[2*t+1], ql[s], kh[2], kh[3]);
            }
        }

        // ---- causal mask (diagonal tile only) ----
        if (kt == qt) {
            int rA = q0 + warp * 16 + (lane >> 2);
#pragma unroll
            for (int f = 0; f < 16; f++) {
                int cb = key0 + f * 8 + ((lane & 3) << 1);
                if (cb     > rA    ) sacc[f][0] = -1e30f;
                if (cb + 1 > rA    ) sacc[f][1] = -1e30f;
                if (cb     > rA + 8) sacc[f][2] = -1e30f;
                if (cb + 1 > rA + 8) sacc[f][3] = -1e30f;
            }
        }

        // ---- max reduce + O rescale (only m-dependent part is serial) ----
        float mtA = -1e30f, mtB = -1e30f;
#pragma unroll
        for (int f = 0; f < 16; f++) {
            mtA = fmaxf(mtA, fmaxf(sacc[f][0], sacc[f][1]));
            mtB = fmaxf(mtB, fmaxf(sacc[f][2], sacc[f][3]));
        }
        mtA = fmaxf(mtA, __shfl_xor_sync(0xffffffffu, mtA, 1));
        mtA = fmaxf(mtA, __shfl_xor_sync(0xffffffffu, mtA, 2));
        mtB = fmaxf(mtB, __shfl_xor_sync(0xffffffffu, mtB, 1));
        mtB = fmaxf(mtB, __shfl_xor_sync(0xffffffffu, mtB, 2));
        float mnA = fmaxf(mA, mtA), mnB = fmaxf(mB, mtB);
        float aA = __expf(mA - mnA), aB = __expf(mB - mnB);
#pragma unroll
        for (int f = 0; f < 8; f++) {
            O[f][0] *= aA; O[f][1] *= aA; O[f][2] *= aB; O[f][3] *= aB;
        }

        // ---- O += P V with LAZY exp (MUFU hides under tensor MMAs) ----
        float rsA = 0.f, rsB = 0.f;
#pragma unroll
        for (int ks = 0; ks < 8; ks++) {
            uint32_t vbh[4][4], vbl[4][4];
            int vrow = ks * 16 + (((lane >> 3) & 1) << 3) + (lane & 7);
#pragma unroll
            for (int t = 0; t < 4; t++) {
                uint32_t off = (uint32_t)(vrow * 144 + (t * 16 + ((lane >> 4) << 3)) * 2);
                LDSM4T(vbh[t], st + 36864 + off);
                LDSM4T(vbl[t], st + 55296 + off);
            }
            float e00 = __expf(sacc[2*ks][0]   - mnA);
            float e01 = __expf(sacc[2*ks][1]   - mnA);
            float e02 = __expf(sacc[2*ks][2]   - mnB);
            float e03 = __expf(sacc[2*ks][3]   - mnB);
            float e10 = __expf(sacc[2*ks+1][0] - mnA);
            float e11 = __expf(sacc[2*ks+1][1] - mnA);
            float e12 = __expf(sacc[2*ks+1][2] - mnB);
            float e13 = __expf(sacc[2*ks+1][3] - mnB);
            rsA += (e00 + e01) + (e10 + e11);
            rsB += (e02 + e03) + (e12 + e13);
            uint32_t ph[4], pl[4];
            ph[0] = packbf(e00, e01); ph[1] = packbf(e02, e03);
            ph[2] = packbf(e10, e11); ph[3] = packbf(e12, e13);
            pl[0] = packbf(e00 - lo16f(ph[0]), e01 - hi16f(ph[0]));
            pl[1] = packbf(e02 - lo16f(ph[1]), e03 - hi16f(ph[1]));
            pl[2] = packbf(e10 - lo16f(ph[2]), e11 - hi16f(ph[2]));
            pl[3] = packbf(e12 - lo16f(ph[3]), e13 - hi16f(ph[3]));
#pragma unroll
            for (int f = 0; f < 8; f++) {
                int t = f >> 1, p = (f & 1) << 1;
                MMA_BF16(O[f], ph, vbh[t][p], vbh[t][p+1]);
                MMA_BF16(O[f], ph, vbl[t][p], vbl[t][p+1]);
                MMA_BF16(O[f], pl, vbh[t][p], vbh[t][p+1]);
            }
        }
        // fold row-sums (off critical path: once per tile)
        rsA += __shfl_xor_sync(0xffffffffu, rsA, 1);
        rsA += __shfl_xor_sync(0xffffffffu, rsA, 2);
        rsB += __shfl_xor_sync(0xffffffffu, rsB, 1);
        rsB += __shfl_xor_sync(0xffffffffu, rsB, 2);
        lA = lA * aA + rsA; mA = mnA;
        lB = lB * aB + rsB; mB = mnB;

        __syncthreads();   // done reading stage kt before it is refilled
    }

    // ---- epilogue: O/l, write preout splits into g_xhi/g_xlo ----
    float iA = __fdividef(1.f, lA), iB = __fdividef(1.f, lB);
    int rA = q0 + warp * 16 + (lane >> 2);
#pragma unroll
    for (int f = 0; f < 8; f++) {
        int colhd = f * 8 + ((lane & 3) << 1);
        size_t ia = ((size_t)b * SEQ + rA) * DMODEL + h * HDIM + colhd;
        size_t ib = ia + (size_t)8 * DMODEL;
        float x0 = O[f][0] * iA, x1 = O[f][1] * iA;
        float x2 = O[f][2] * iB, x3 = O[f][3] * iB;
        uint32_t hA = packbf(x0, x1);
        uint32_t lAw = packbf(x0 - lo16f(hA), x1 - hi16f(hA));
        uint32_t hB = packbf(x2, x3);
        uint32_t lBw = packbf(x2 - lo16f(hB), x3 - hi16f(hB));
        *(uint32_t*)&g_xhi[ia] = hA; *(uint32_t*)&g_xlo[ia] = lAw;
        *(uint32_t*)&g_xhi[ib] = hB; *(uint32_t*)&g_xlo[ib] = lBw;
    }
}

// =================================================================
extern "C" void kernel_launch(void* const* d_in, const int* in_sizes, int n_in,
                              void* d_out, int out_size)
{
    (void)in_sizes; (void)n_in; (void)out_size;
    const float* x  = (const float*)d_in[0];
    const float* Wq = (const float*)d_in[1];
    const float* bq = (const float*)d_in[2];
    const float* Wk = (const float*)d_in[3];
    const float* bk = (const float*)d_in[4];
    const float* Wv = (const float*)d_in[5];
    const float* bv = (const float*)d_in[6];
    const float* Wo = (const float*)d_in[7];
    const float* bo = (const float*)d_in[8];
    float* out = (float*)d_out;

    void *pxh, *pxl;
    cudaGetSymbolAddress(&pxh, g_xhi); cudaGetSymbolAddress(&pxl, g_xlo);
    __nv_bfloat16* xhi = (__nv_bfloat16*)pxh;
    __nv_bfloat16* xlo = (__nv_bfloat16*)pxl;

    cudaFuncSetAttribute(mma_qkv_kernel,
                         cudaFuncAttributeMaxDynamicSharedMemorySize, GEMM_SMEM);
    cudaFuncSetAttribute(mma_oproj_kernel,
                         cudaFuncAttributeMaxDynamicSharedMemorySize, GEMM_SMEM);
    cudaFuncSetAttribute(flash_tc_kernel,
                         cudaFuncAttributeMaxDynamicSharedMemorySize, FL_SMEM);

    // ---- split conversions ----
    const int XN4 = NTOK * DMODEL / 4;
    const int WN4 = (int)((size_t)DMODEL * DMODEL / 4);
    split_kernel<<<XN4 / 256, 256>>>(x, xhi, xlo, XN4);
    dim3 gw(WN4 / 256, 4);
    split_w4_kernel<<<gw, 256>>>(Wq, Wk, Wv, Wo, WN4);

    // ---- fused QKV projection ----
    dim3 gq(NTOK / 128, 3 * NHEAD);        // 64 x 36
    mma_qkv_kernel<<<gq, 256, GEMM_SMEM>>>(bq, bk, bv);

    // ---- tensor-core flash attention (writes preout splits to xhi/xlo) ----
    dim3 gf(SEQ / 128, NHEAD, BATCH);      // 32 x 12 x 2
    flash_tc_kernel<<<gf, 256, FL_SMEM>>>();

    // ---- output projection ----
    dim3 go(NTOK / 128, DMODEL / 64);      // 64 x 12
    mma_oproj_kernel<<<go, 256, GEMM_SMEM>>>(bo, out);
}